// round 13
// baseline (speedup 1.0000x reference)
#include <cuda_runtime.h>

#define BB 8
#define EE 64
#define MM 128
#define DD 256
#define HH 8
#define DKK 32
#define NPAIR (EE*EE)
#define SETHALF (BB*NPAIR*DD)

typedef unsigned long long ull;

// ---- packed fp32x2 helpers ----
__device__ __forceinline__ void fma2(ull &d, ull a, ull b) {
    asm("fma.rn.f32x2 %0, %1, %2, %0;" : "+l"(d) : "l"(a), "l"(b));
}
__device__ __forceinline__ ull bcast2(float x) {
    ull d;
    asm("mov.b64 %0, {%1, %1};" : "=l"(d) : "r"(__float_as_uint(x)));
    return d;
}
__device__ __forceinline__ float2 unpack2(ull v) {
    float2 r;
    asm("mov.b64 {%0, %1}, %2;" : "=f"(r.x), "=f"(r.y) : "l"(v));
    return r;
}
// ---- cp.async ----
__device__ __forceinline__ void cp_async16(unsigned dst, const void* src) {
    asm volatile("cp.async.cg.shared.global [%0], [%1], 16;" :: "r"(dst), "l"(src));
}
__device__ __forceinline__ void cp_commit() { asm volatile("cp.async.commit_group;"); }
__device__ __forceinline__ void cp_wait0()  { asm volatile("cp.async.wait_group 0;" ::: "memory"); }

// ---------------- scratch ----------------
__device__ float g_q[2][BB*EE*DD];
__device__ float g_k[2][BB*MM*DD];
__device__ float g_v[2][BB*MM*DD];
__device__ float g_q2[2][BB*EE*DD];
__device__ float g_k2[2][BB*MM*DD];
__device__ float g_v2[2][BB*MM*DD];
__device__ float g_u[2][BB*HH*MM*DD];
__device__ float g_S[2][BB*HH*MM*EE];    // [s][b][h][m][j], j innermost
__device__ float g_usum[2][BB*DD];
__device__ int   g_cnt[BB*EE];
__device__ int   g_list[BB*EE*MM];

// ---- merged projections; col-pair acc packing (W read as ull pairs, no W bcast) ----
// grid (8, 6, 8): x = colTile(0..3) + kh*4; y 0..4 = job/rowTile; y==5 & x==0 = lists.
__global__ __launch_bounds__(256) void k_gemm_all(
    const float* __restrict__ entities, const float* __restrict__ mentions,
    const float* __restrict__ sentences, const int* __restrict__ sent_ids,
    const int* __restrict__ eid,
    const float* __restrict__ W_h, const float* __restrict__ b_h,
    const float* __restrict__ W_t, const float* __restrict__ b_t)
{
    __shared__ float a_sh[2][32][68];
    __shared__ float w_sh[2][2][32][64];
    int b = blockIdx.z;
    int y = blockIdx.y;
    int x = blockIdx.x;
    int colTile = x & 3;
    int kh = x >> 2;
    int tid = threadIdx.x;

    if (y == 5) {
        if (x == 0 && tid < EE) {
            int e = tid;
            int cnt = 0;
            for (int m = 0; m < MM; m++)
                if (eid[b*MM + m] == e) g_list[(b*EE + e)*MM + cnt++] = m;
            g_cnt[b*EE + e] = cnt;
        }
        return;
    }

    int job, rowTile;
    if (y == 0) { job = 0; rowTile = 0; }
    else if (y <= 2) { job = 1; rowTile = y - 1; }
    else { job = 2; rowTile = y - 3; }
    const float* A; int rows, woff, boff;
    float *C0, *C1;
    bool indirect = false;
    switch (job) {
      case 0:
        A = entities; rows = EE;  woff = 0;      boff = 0;
        C0 = kh ? g_q2[0] : g_q[0]; C1 = kh ? g_q2[1] : g_q[1]; break;
      case 1:
        A = nullptr;  rows = MM;  woff = 65536;  boff = 256; indirect = true;
        C0 = kh ? g_k2[0] : g_k[0]; C1 = kh ? g_k2[1] : g_k[1]; break;
      default:
        A = mentions; rows = MM;  woff = 131072; boff = 512;
        C0 = kh ? g_v2[0] : g_v[0]; C1 = kh ? g_v2[1] : g_v[1]; break;
    }
    int row0 = rowTile * 64;
    int col0 = colTile * 64;
    int kbase = kh * 128;

    int kqI[2], cI[2];
    const float* rp[2];
    #pragma unroll
    for (int i = 0; i < 2; i++) {
        int f = tid * 2 + i;
        int r = f >> 3;
        kqI[i] = (f & 7) * 4;
        cI[i]  = r ^ (((kqI[i] >> 3) & 3) << 3);
        if (indirect) {
            int sid = sent_ids[b * MM + row0 + r];
            rp[i] = sentences + ((size_t)(b * 32 + sid)) * DD + kbase + kqI[i];
        } else {
            rp[i] = A + ((size_t)b * rows + row0 + r) * DD + kbase + kqI[i];
        }
    }
    unsigned wbase = (unsigned)__cvta_generic_to_shared(&w_sh[0][0][0][0]);
    const unsigned WBUF = 2u * 32u * 64u * 4u;
    unsigned wdst[4];
    const float* wp[4];
    #pragma unroll
    for (int j = 0; j < 4; j++) {
        int idx = tid + j * 256;
        int ws = idx >> 9;
        int rem = idx & 511;
        int wk = rem >> 4;
        int wd = (rem & 15) * 4;
        wdst[j] = wbase + (unsigned)(((ws * 32 + wk) * 64 + wd) * 4);
        const float* Wsel = (ws ? W_t : W_h) + woff;
        wp[j] = Wsel + (size_t)(kbase + wk) * DD + col0 + wd;
    }

    int rg = tid & 15;
    int cg = tid >> 4;
    int rb = rg * 4;
    ull acc[2][4][2];     // [set][row][colpair]
    #pragma unroll
    for (int s = 0; s < 2; s++)
        #pragma unroll
        for (int r = 0; r < 4; r++)
            { acc[s][r][0] = 0ull; acc[s][r][1] = 0ull; }

    #pragma unroll
    for (int j = 0; j < 4; j++) cp_async16(wdst[j], wp[j]);
    cp_commit();
    {
        float4 pa0 = *(const float4*)(rp[0]);
        float4 pa1 = *(const float4*)(rp[1]);
        a_sh[0][kqI[0]+0][cI[0]] = pa0.x; a_sh[0][kqI[0]+1][cI[0]] = pa0.y;
        a_sh[0][kqI[0]+2][cI[0]] = pa0.z; a_sh[0][kqI[0]+3][cI[0]] = pa0.w;
        a_sh[0][kqI[1]+0][cI[1]] = pa1.x; a_sh[0][kqI[1]+1][cI[1]] = pa1.y;
        a_sh[0][kqI[1]+2][cI[1]] = pa1.z; a_sh[0][kqI[1]+3][cI[1]] = pa1.w;
    }
    cp_wait0();
    __syncthreads();

    float4 pa[2];
    #pragma unroll
    for (int kc = 0; kc < 4; kc++) {
        int buf = kc & 1;
        int nb = buf ^ 1;
        if (kc < 3) {
            int k0n = (kc + 1) * 32;
            #pragma unroll
            for (int j = 0; j < 4; j++)
                cp_async16(wdst[j] + (unsigned)nb * WBUF, wp[j] + (size_t)k0n * DD);
            cp_commit();
            #pragma unroll
            for (int i = 0; i < 2; i++) pa[i] = *(const float4*)(rp[i] + k0n);
        }
        #pragma unroll
        for (int kk = 0; kk < 24; kk++) {
            int cs = rb ^ (((kk >> 3) & 3) << 3);
            float4 Af = *(const float4*)&a_sh[buf][kk][cs];
            ulonglong2 W0 = *(const ulonglong2*)&w_sh[buf][0][kk][cg * 4];
            ulonglong2 W1 = *(const ulonglong2*)&w_sh[buf][1][kk][cg * 4];
            ull a0 = bcast2(Af.x), a1 = bcast2(Af.y), a2 = bcast2(Af.z), a3 = bcast2(Af.w);
            fma2(acc[0][0][0], a0, W0.x); fma2(acc[0][0][1], a0, W0.y);
            fma2(acc[0][1][0], a1, W0.x); fma2(acc[0][1][1], a1, W0.y);
            fma2(acc[0][2][0], a2, W0.x); fma2(acc[0][2][1], a2, W0.y);
            fma2(acc[0][3][0], a3, W0.x); fma2(acc[0][3][1], a3, W0.y);
            fma2(acc[1][0][0], a0, W1.x); fma2(acc[1][0][1], a0, W1.y);
            fma2(acc[1][1][0], a1, W1.x); fma2(acc[1][1][1], a1, W1.y);
            fma2(acc[1][2][0], a2, W1.x); fma2(acc[1][2][1], a2, W1.y);
            fma2(acc[1][3][0], a3, W1.x); fma2(acc[1][3][1], a3, W1.y);
        }
        if (kc < 3) {
            #pragma unroll
            for (int i = 0; i < 2; i++) {
                a_sh[nb][kqI[i]+0][cI[i]] = pa[i].x; a_sh[nb][kqI[i]+1][cI[i]] = pa[i].y;
                a_sh[nb][kqI[i]+2][cI[i]] = pa[i].z; a_sh[nb][kqI[i]+3][cI[i]] = pa[i].w;
            }
        }
        #pragma unroll
        for (int kk = 24; kk < 32; kk++) {
            int cs = rb ^ (((kk >> 3) & 3) << 3);
            float4 Af = *(const float4*)&a_sh[buf][kk][cs];
            ulonglong2 W0 = *(const ulonglong2*)&w_sh[buf][0][kk][cg * 4];
            ulonglong2 W1 = *(const ulonglong2*)&w_sh[buf][1][kk][cg * 4];
            ull a0 = bcast2(Af.x), a1 = bcast2(Af.y), a2 = bcast2(Af.z), a3 = bcast2(Af.w);
            fma2(acc[0][0][0], a0, W0.x); fma2(acc[0][0][1], a0, W0.y);
            fma2(acc[0][1][0], a1, W0.x); fma2(acc[0][1][1], a1, W0.y);
            fma2(acc[0][2][0], a2, W0.x); fma2(acc[0][2][1], a2, W0.y);
            fma2(acc[0][3][0], a3, W0.x); fma2(acc[0][3][1], a3, W0.y);
            fma2(acc[1][0][0], a0, W1.x); fma2(acc[1][0][1], a0, W1.y);
            fma2(acc[1][1][0], a1, W1.x); fma2(acc[1][1][1], a1, W1.y);
            fma2(acc[1][2][0], a2, W1.x); fma2(acc[1][2][1], a2, W1.y);
            fma2(acc[1][3][0], a3, W1.x); fma2(acc[1][3][1], a3, W1.y);
        }
        if (kc < 3) cp_wait0();
        __syncthreads();
    }

    #pragma unroll
    for (int s = 0; s < 2; s++) {
        float* C = s ? C1 : C0;
        float4 bi = make_float4(0.f, 0.f, 0.f, 0.f);
        if (kh == 0) {
            const float* bias = (s ? b_t : b_h) + boff;
            bi = *(const float4*)(bias + col0 + cg * 4);
        }
        #pragma unroll
        for (int r = 0; r < 4; r++) {
            float2 p0 = unpack2(acc[s][r][0]);
            float2 p1 = unpack2(acc[s][r][1]);
            int row = row0 + rg * 4 + r;
            float4 o = make_float4(p0.x + bi.x, p0.y + bi.y, p1.x + bi.z, p1.y + bi.w);
            *(float4*)(C + ((size_t)b * rows + row) * DD + col0 + cg * 4) = o;
        }
    }
}

// ---------------- mid: uproj (256) + usum (16) + scores (128); sums K-split partials
__global__ __launch_bounds__(256) void k_mid(const float* __restrict__ W_h,
                                             const float* __restrict__ W_t)
{
    __shared__ __align__(16) char buf[33792];
    int blk = blockIdx.x;
    int tid = threadIdx.x;

    if (blk < 256) {
        int ct = blk & 1;
        int g = blk >> 1;
        int s = g >> 6, b = (g >> 3) & 7, h = g & 7;
        const float* Wo = (s ? W_t : W_h) + 3 * 65536 + h * DKK * DD;
        const float* V  = g_v[s]  + (size_t)b * MM * DD + h * DKK;
        const float* V2 = g_v2[s] + (size_t)b * MM * DD + h * DKK;
        int col0 = ct * 128;
        float (*a_sh)[132] = (float(*)[132])buf;
        float (*w_sh)[128] = (float(*)[128])(buf + 16896);

        #pragma unroll
        for (int i = 0; i < 4; i++) {
            int f = tid + i * 256;
            int r = f >> 3;
            int kq = (f & 7) * 4;
            float4 a0 = *(const float4*)(V  + (size_t)r * DD + kq);
            float4 a1 = *(const float4*)(V2 + (size_t)r * DD + kq);
            a_sh[kq+0][r] = a0.x + a1.x; a_sh[kq+1][r] = a0.y + a1.y;
            a_sh[kq+2][r] = a0.z + a1.z; a_sh[kq+3][r] = a0.w + a1.w;
        }
        #pragma unroll
        for (int i = 0; i < 4; i++) {
            int idx = tid + i * 256;
            int kk = idx >> 5;
            int dq = (idx & 31) * 4;
            *(float4*)&w_sh[kk][dq] = *(const float4*)(Wo + (size_t)kk * DD + col0 + dq);
        }
        __syncthreads();

        int rg = tid & 15;
        int cg = tid >> 4;
        ull acc[4][8];
        #pragma unroll
        for (int p = 0; p < 4; p++)
            #pragma unroll
            for (int c = 0; c < 8; c++) acc[p][c] = 0ull;
        #pragma unroll
        for (int kk = 0; kk < 32; kk++) {
            ulonglong2 A0 = *(const ulonglong2*)&a_sh[kk][rg * 8];
            ulonglong2 A1 = *(const ulonglong2*)&a_sh[kk][rg * 8 + 4];
            float4 wa = *(const float4*)&w_sh[kk][cg * 8];
            float4 wb = *(const float4*)&w_sh[kk][cg * 8 + 4];
            ull wp[8] = { bcast2(wa.x), bcast2(wa.y), bcast2(wa.z), bcast2(wa.w),
                          bcast2(wb.x), bcast2(wb.y), bcast2(wb.z), bcast2(wb.w) };
            #pragma unroll
            for (int c = 0; c < 8; c++) {
                fma2(acc[0][c], A0.x, wp[c]);
                fma2(acc[1][c], A0.y, wp[c]);
                fma2(acc[2][c], A1.x, wp[c]);
                fma2(acc[3][c], A1.y, wp[c]);
            }
        }
        float* U = g_u[s] + ((size_t)(b * HH + h) * MM) * DD;
        #pragma unroll
        for (int p = 0; p < 4; p++) {
            float2 u0 = unpack2(acc[p][0]), u1 = unpack2(acc[p][1]);
            float2 u2 = unpack2(acc[p][2]), u3 = unpack2(acc[p][3]);
            float2 u4 = unpack2(acc[p][4]), u5 = unpack2(acc[p][5]);
            float2 u6 = unpack2(acc[p][6]), u7 = unpack2(acc[p][7]);
            int re = rg * 8 + 2 * p;
            float* d0 = U + (size_t)re * DD + col0 + cg * 8;
            float* d1 = d0 + DD;
            *(float4*)(d0)     = make_float4(u0.x, u1.x, u2.x, u3.x);
            *(float4*)(d0 + 4) = make_float4(u4.x, u5.x, u6.x, u7.x);
            *(float4*)(d1)     = make_float4(u0.y, u1.y, u2.y, u3.y);
            *(float4*)(d1 + 4) = make_float4(u4.y, u5.y, u6.y, u7.y);
        }
    } else if (blk < 272) {
        int id = blk - 256;
        int b = id & 7, s = id >> 3;
        const float* Wo = (s ? W_t : W_h) + 3 * 65536;
        float* vs = (float*)buf;
        int d = tid;
        const float* v  = g_v[s]  + (size_t)b * MM * DD;
        const float* v2 = g_v2[s] + (size_t)b * MM * DD;
        float sum = 0.f;
        for (int m = 0; m < MM; m++) sum += v[m * DD + d] + v2[m * DD + d];
        vs[d] = sum;
        __syncthreads();
        float o = 0.f;
        for (int k = 0; k < DD; k++) o = fmaf(vs[k], Wo[(size_t)k * DD + d], o);
        g_usum[s][b * DD + d] = o;
    } else {
        int t = blk - 272;
        int h = t & 7, b = (t >> 3) & 7, s = t >> 6;
        float (*qs)[DKK + 1] = (float(*)[DKK + 1])buf;
        float (*ks)[DKK + 1] = (float(*)[DKK + 1])(buf + EE * (DKK + 1) * 4);
        const float* q  = g_q[s]  + (size_t)b * EE * DD + h * DKK;
        const float* q2 = g_q2[s] + (size_t)b * EE * DD + h * DKK;
        const float* k  = g_k[s]  + (size_t)b * MM * DD + h * DKK;
        const float* k2 = g_k2[s] + (size_t)b * MM * DD + h * DKK;
        for (int i = tid; i < EE * DKK; i += 256) {
            int r = i >> 5, c = i & 31;
            qs[r][c] = q[r * DD + c] + q2[r * DD + c];
        }
        for (int i = tid; i < MM * DKK; i += 256) {
            int r = i >> 5, c = i & 31;
            ks[r][c] = k[r * DD + c] + k2[r * DD + c];
        }
        __syncthreads();
        int j = tid & 63;
        int m0 = tid >> 6;
        float* Sbase = g_S[s] + (size_t)(b * HH + h) * MM * EE;
        const float scale = 0.17677669529663687f;
        for (int m = m0; m < MM; m += 4) {
            float acc = 0.f;
            #pragma unroll
            for (int c = 0; c < DKK; c++) acc = fmaf(qs[j][c], ks[m][c], acc);
            Sbase[(size_t)m * EE + j] = acc * scale;
        }
    }
}

// -------- fused output v5: D-SPLIT (disjoint u halves, no duplicate u reads) --------
// grid (EE, BB, 4): z = s*2 + dhalf. Per block: full 64 j x 128 d.
__global__ __launch_bounds__(256, 3) void k_out3(const float* __restrict__ b_h,
                                                 const float* __restrict__ b_t,
                                                 float* __restrict__ out)
{
    int i = blockIdx.x;
    int b = blockIdx.y;
    int z = blockIdx.z;
    int s = z >> 1;
    int dh = (z & 1) * 128;
    const float* bo = (s ? b_t : b_h) + 3 * 256 + dh;
    float* outS = out + (size_t)s * SETHALF + (size_t)b * NPAIR * DD + dh;
    int tid = threadIdx.x;
    int cnt = g_cnt[b * EE + i];

    if (cnt == 0) {
        const float* us = g_usum[s] + b * DD + dh;
        for (int idx = tid; idx < EE * 32; idx += 256) {
            int j = idx >> 5;
            int q = idx & 31;
            float4 bo4 = *(const float4*)(bo + q * 4);
            float4 u4 = *(const float4*)(us + q * 4);
            float4 o = make_float4(bo4.x + u4.x * (1.0f/128.0f),
                                   bo4.y + u4.y * (1.0f/128.0f),
                                   bo4.z + u4.z * (1.0f/128.0f),
                                   bo4.w + u4.w * (1.0f/128.0f));
            int pair = (s == 0) ? (i * EE + j) : (j * EE + i);
            *(float4*)(outS + (size_t)pair * DD + q * 4) = o;
        }
        return;
    }

    __shared__ int lst[MM];
    __shared__ float mx[HH][EE];
    __shared__ float rs[HH][EE];
    __shared__ float wsh[HH][4][EE];   // 8 KB
    __shared__ float4 sU[HH][4][32];   // 16 KB: d-half u rows

    for (int t = tid; t < cnt; t += 256) lst[t] = g_list[(b * EE + i) * MM + t];
    __syncthreads();

    const float* Sb = g_S[s] + (size_t)(b * HH) * MM * EE;

    // online softmax stats: 512 (h,j) tasks, 2/thread, coalesced S rows
    for (int task = tid; task < HH * EE; task += 256) {
        int h = task >> 6, j = task & 63;
        const float* Sh = Sb + (size_t)h * MM * EE + j;
        float m_ = -1e30f, se = 0.f;
        for (int c = 0; c < cnt; c++) {
            float v = Sh[(size_t)lst[c] * EE];
            float nm = fmaxf(m_, v);
            se = se * __expf(m_ - nm) + __expf(v - nm);
            m_ = nm;
        }
        mx[h][j] = m_;
        rs[h][j] = 1.0f / se;
    }
    __syncthreads();

    int dq = tid & 31;    // d = dh + dq*4 .. +3
    int jg = tid >> 5;    // j = jg*8 .. +7
    ull acc[8][2];
    #pragma unroll
    for (int jj = 0; jj < 8; jj++) { acc[jj][0] = 0ull; acc[jj][1] = 0ull; }

    const float* Ug = g_u[s] + (size_t)(b * HH) * MM * DD + dh;

    for (int base = 0; base < cnt; base += 4) {
        int ce = min(4, cnt - base);
        // stage u d-half rows: 1024 float4, 4/thread
        #pragma unroll
        for (int rr = 0; rr < 4; rr++) {
            int t = tid + rr * 256;
            int h = t >> 7, c = (t >> 5) & 3, q = t & 31;
            if (c < ce)
                sU[h][c][q] = *(const float4*)(Ug + ((size_t)h * MM + lst[base + c]) * DD + q * 4);
        }
        // weights: 2048 entries, 8/thread
        for (int t = tid; t < HH * 4 * EE; t += 256) {
            int h = t >> 8, c = (t >> 6) & 3, j = t & 63;
            if (c < ce) {
                float sv = Sb[((size_t)h * MM + lst[base + c]) * EE + j];
                wsh[h][c][j] = __expf(sv - mx[h][j]) * rs[h][j];
            }
        }
        __syncthreads();
        for (int c = 0; c < ce; c++) {
            #pragma unroll
            for (int h = 0; h < HH; h++) {
                ulonglong2 U = *(const ulonglong2*)&sU[h][c][dq];
                const float* wr = &wsh[h][c][jg * 8];
                float4 wa = *(const float4*)(wr);
                float4 wb = *(const float4*)(wr + 4);
                ull w0 = bcast2(wa.x), w1 = bcast2(wa.y), w2 = bcast2(wa.z), w3 = bcast2(wa.w);
                fma2(acc[0][0], w0, U.x); fma2(acc[0][1], w0, U.y);
                fma2(acc[1][0], w1, U.x); fma2(acc[1][1], w1, U.y);
                fma2(acc[2][0], w2, U.x); fma2(acc[2][1], w2, U.y);
                fma2(acc[3][0], w3, U.x); fma2(acc[3][1], w3, U.y);
                ull w4 = bcast2(wb.x), w5 = bcast2(wb.y), w6 = bcast2(wb.z), w7 = bcast2(wb.w);
                fma2(acc[4][0], w4, U.x); fma2(acc[4][1], w4, U.y);
                fma2(acc[5][0], w5, U.x); fma2(acc[5][1], w5, U.y);
                fma2(acc[6][0], w6, U.x); fma2(acc[6][1], w6, U.y);
                fma2(acc[7][0], w7, U.x); fma2(acc[7][1], w7, U.y);
            }
        }
        __syncthreads();
    }

    float4 bo4 = *(const float4*)(bo + dq * 4);
    #pragma unroll
    for (int jj = 0; jj < 8; jj++) {
        int j = jg * 8 + jj;
        int pair = (s == 0) ? (i * EE + j) : (j * EE + i);
        float2 p0 = unpack2(acc[jj][0]);
        float2 p1 = unpack2(acc[jj][1]);
        float4 o = make_float4(p0.x + bo4.x, p0.y + bo4.y, p1.x + bo4.z, p1.y + bo4.w);
        *(float4*)(outS + (size_t)pair * DD + dq * 4) = o;
    }
}

// ---------------- launch ----------------
extern "C" void kernel_launch(void* const* d_in, const int* in_sizes, int n_in,
                              void* d_out, int out_size) {
    const float* entities  = (const float*)d_in[0];
    const float* mentions  = (const float*)d_in[1];
    const float* sentences = (const float*)d_in[2];
    const int*   sent_ids  = (const int*)d_in[3];
    const int*   eid       = (const int*)d_in[4];
    const float* W_h       = (const float*)d_in[5];
    const float* b_h       = (const float*)d_in[6];
    const float* W_t       = (const float*)d_in[7];
    const float* b_t       = (const float*)d_in[8];
    float* out = (float*)d_out;

    k_gemm_all<<<dim3(8, 6, BB), 256>>>(entities, mentions, sentences, sent_ids, eid,
                                        W_h, b_h, W_t, b_t);
    k_mid<<<400, 256>>>(W_h, W_t);
    k_out3<<<dim3(EE, BB, 4), 256>>>(b_h, b_t, out);
}

// round 14
// speedup vs baseline: 1.0389x; 1.0389x over previous
#include <cuda_runtime.h>

#define BB 8
#define EE 64
#define MM 128
#define DD 256
#define HH 8
#define DKK 32
#define NPAIR (EE*EE)
#define SETHALF (BB*NPAIR*DD)

typedef unsigned long long ull;

// ---- packed fp32x2 helpers ----
__device__ __forceinline__ void fma2(ull &d, ull a, ull b) {
    asm("fma.rn.f32x2 %0, %1, %2, %0;" : "+l"(d) : "l"(a), "l"(b));
}
__device__ __forceinline__ ull bcast2(float x) {
    ull d;
    asm("mov.b64 %0, {%1, %1};" : "=l"(d) : "r"(__float_as_uint(x)));
    return d;
}
__device__ __forceinline__ float2 unpack2(ull v) {
    float2 r;
    asm("mov.b64 {%0, %1}, %2;" : "=f"(r.x), "=f"(r.y) : "l"(v));
    return r;
}
// ---- cp.async ----
__device__ __forceinline__ void cp_async16(unsigned dst, const void* src) {
    asm volatile("cp.async.cg.shared.global [%0], [%1], 16;" :: "r"(dst), "l"(src));
}
__device__ __forceinline__ void cp_commit() { asm volatile("cp.async.commit_group;"); }
__device__ __forceinline__ void cp_wait0()  { asm volatile("cp.async.wait_group 0;" ::: "memory"); }

// ---------------- scratch ----------------
__device__ float g_q[2][BB*EE*DD];
__device__ float g_k[2][BB*MM*DD];
__device__ float g_v[2][BB*MM*DD];
__device__ float g_q2[2][BB*EE*DD];
__device__ float g_k2[2][BB*MM*DD];
__device__ float g_v2[2][BB*MM*DD];
__device__ float g_u[2][BB*HH*MM*DD];
__device__ float g_S[2][BB*HH*MM*EE];    // [s][b][h][m][j], j innermost
__device__ float g_usum[2][BB*DD];
__device__ int   g_cnt[BB*EE];
__device__ int   g_list[BB*EE*MM];

// ---- merged projections; WARP-UNIFORM row map: rg = tid>>4 (A reads broadcast) ----
// grid (8, 6, 8): x = colTile(0..3) + kh*4; y 0..4 = job/rowTile; y==5 & x==0 = lists.
__global__ __launch_bounds__(256) void k_gemm_all(
    const float* __restrict__ entities, const float* __restrict__ mentions,
    const float* __restrict__ sentences, const int* __restrict__ sent_ids,
    const int* __restrict__ eid,
    const float* __restrict__ W_h, const float* __restrict__ b_h,
    const float* __restrict__ W_t, const float* __restrict__ b_t)
{
    __shared__ float a_sh[2][32][68];
    __shared__ float w_sh[2][2][32][64];
    int b = blockIdx.z;
    int y = blockIdx.y;
    int x = blockIdx.x;
    int colTile = x & 3;
    int kh = x >> 2;
    int tid = threadIdx.x;

    if (y == 5) {
        if (x == 0 && tid < EE) {
            int e = tid;
            int cnt = 0;
            for (int m = 0; m < MM; m++)
                if (eid[b*MM + m] == e) g_list[(b*EE + e)*MM + cnt++] = m;
            g_cnt[b*EE + e] = cnt;
        }
        return;
    }

    int job, rowTile;
    if (y == 0) { job = 0; rowTile = 0; }
    else if (y <= 2) { job = 1; rowTile = y - 1; }
    else { job = 2; rowTile = y - 3; }
    const float* A; int rows, woff, boff;
    float *C0, *C1;
    bool indirect = false;
    switch (job) {
      case 0:
        A = entities; rows = EE;  woff = 0;      boff = 0;
        C0 = kh ? g_q2[0] : g_q[0]; C1 = kh ? g_q2[1] : g_q[1]; break;
      case 1:
        A = nullptr;  rows = MM;  woff = 65536;  boff = 256; indirect = true;
        C0 = kh ? g_k2[0] : g_k[0]; C1 = kh ? g_k2[1] : g_k[1]; break;
      default:
        A = mentions; rows = MM;  woff = 131072; boff = 512;
        C0 = kh ? g_v2[0] : g_v[0]; C1 = kh ? g_v2[1] : g_v[1]; break;
    }
    int row0 = rowTile * 64;
    int col0 = colTile * 64;
    int kbase = kh * 128;

    int kqI[2], cI[2];
    const float* rp[2];
    #pragma unroll
    for (int i = 0; i < 2; i++) {
        int f = tid * 2 + i;
        int r = f >> 3;
        kqI[i] = (f & 7) * 4;
        cI[i]  = r ^ (((kqI[i] >> 3) & 3) << 3);
        if (indirect) {
            int sid = sent_ids[b * MM + row0 + r];
            rp[i] = sentences + ((size_t)(b * 32 + sid)) * DD + kbase + kqI[i];
        } else {
            rp[i] = A + ((size_t)b * rows + row0 + r) * DD + kbase + kqI[i];
        }
    }
    unsigned wbase = (unsigned)__cvta_generic_to_shared(&w_sh[0][0][0][0]);
    const unsigned WBUF = 2u * 32u * 64u * 4u;
    unsigned wdst[4];
    const float* wp[4];
    #pragma unroll
    for (int j = 0; j < 4; j++) {
        int idx = tid + j * 256;
        int ws = idx >> 9;
        int rem = idx & 511;
        int wk = rem >> 4;
        int wd = (rem & 15) * 4;
        wdst[j] = wbase + (unsigned)(((ws * 32 + wk) * 64 + wd) * 4);
        const float* Wsel = (ws ? W_t : W_h) + woff;
        wp[j] = Wsel + (size_t)(kbase + wk) * DD + col0 + wd;
    }

    // WARP-UNIFORM map: lanes 0-15 & 16-31 mirror cols; rows warp-paired (A broadcast)
    int rg = tid >> 4;    // 16 row groups x 4 rows
    int cg = tid & 15;    // 16 col groups x 4 cols
    int rb = rg * 4;
    ull acc[2][4][2];     // [set][row][colpair]
    #pragma unroll
    for (int s = 0; s < 2; s++)
        #pragma unroll
        for (int r = 0; r < 4; r++)
            { acc[s][r][0] = 0ull; acc[s][r][1] = 0ull; }

    #pragma unroll
    for (int j = 0; j < 4; j++) cp_async16(wdst[j], wp[j]);
    cp_commit();
    {
        float4 pa0 = *(const float4*)(rp[0]);
        float4 pa1 = *(const float4*)(rp[1]);
        a_sh[0][kqI[0]+0][cI[0]] = pa0.x; a_sh[0][kqI[0]+1][cI[0]] = pa0.y;
        a_sh[0][kqI[0]+2][cI[0]] = pa0.z; a_sh[0][kqI[0]+3][cI[0]] = pa0.w;
        a_sh[0][kqI[1]+0][cI[1]] = pa1.x; a_sh[0][kqI[1]+1][cI[1]] = pa1.y;
        a_sh[0][kqI[1]+2][cI[1]] = pa1.z; a_sh[0][kqI[1]+3][cI[1]] = pa1.w;
    }
    cp_wait0();
    __syncthreads();

    float4 pa[2];
    #pragma unroll
    for (int kc = 0; kc < 4; kc++) {
        int buf = kc & 1;
        int nb = buf ^ 1;
        if (kc < 3) {
            int k0n = (kc + 1) * 32;
            #pragma unroll
            for (int j = 0; j < 4; j++)
                cp_async16(wdst[j] + (unsigned)nb * WBUF, wp[j] + (size_t)k0n * DD);
            cp_commit();
            #pragma unroll
            for (int i = 0; i < 2; i++) pa[i] = *(const float4*)(rp[i] + k0n);
        }
        #pragma unroll
        for (int kk = 0; kk < 24; kk++) {
            int cs = rb ^ (((kk >> 3) & 3) << 3);
            float4 Af = *(const float4*)&a_sh[buf][kk][cs];
            ulonglong2 W0 = *(const ulonglong2*)&w_sh[buf][0][kk][cg * 4];
            ulonglong2 W1 = *(const ulonglong2*)&w_sh[buf][1][kk][cg * 4];
            ull a0 = bcast2(Af.x), a1 = bcast2(Af.y), a2 = bcast2(Af.z), a3 = bcast2(Af.w);
            fma2(acc[0][0][0], a0, W0.x); fma2(acc[0][0][1], a0, W0.y);
            fma2(acc[0][1][0], a1, W0.x); fma2(acc[0][1][1], a1, W0.y);
            fma2(acc[0][2][0], a2, W0.x); fma2(acc[0][2][1], a2, W0.y);
            fma2(acc[0][3][0], a3, W0.x); fma2(acc[0][3][1], a3, W0.y);
            fma2(acc[1][0][0], a0, W1.x); fma2(acc[1][0][1], a0, W1.y);
            fma2(acc[1][1][0], a1, W1.x); fma2(acc[1][1][1], a1, W1.y);
            fma2(acc[1][2][0], a2, W1.x); fma2(acc[1][2][1], a2, W1.y);
            fma2(acc[1][3][0], a3, W1.x); fma2(acc[1][3][1], a3, W1.y);
        }
        if (kc < 3) {
            #pragma unroll
            for (int i = 0; i < 2; i++) {
                a_sh[nb][kqI[i]+0][cI[i]] = pa[i].x; a_sh[nb][kqI[i]+1][cI[i]] = pa[i].y;
                a_sh[nb][kqI[i]+2][cI[i]] = pa[i].z; a_sh[nb][kqI[i]+3][cI[i]] = pa[i].w;
            }
        }
        #pragma unroll
        for (int kk = 24; kk < 32; kk++) {
            int cs = rb ^ (((kk >> 3) & 3) << 3);
            float4 Af = *(const float4*)&a_sh[buf][kk][cs];
            ulonglong2 W0 = *(const ulonglong2*)&w_sh[buf][0][kk][cg * 4];
            ulonglong2 W1 = *(const ulonglong2*)&w_sh[buf][1][kk][cg * 4];
            ull a0 = bcast2(Af.x), a1 = bcast2(Af.y), a2 = bcast2(Af.z), a3 = bcast2(Af.w);
            fma2(acc[0][0][0], a0, W0.x); fma2(acc[0][0][1], a0, W0.y);
            fma2(acc[0][1][0], a1, W0.x); fma2(acc[0][1][1], a1, W0.y);
            fma2(acc[0][2][0], a2, W0.x); fma2(acc[0][2][1], a2, W0.y);
            fma2(acc[0][3][0], a3, W0.x); fma2(acc[0][3][1], a3, W0.y);
            fma2(acc[1][0][0], a0, W1.x); fma2(acc[1][0][1], a0, W1.y);
            fma2(acc[1][1][0], a1, W1.x); fma2(acc[1][1][1], a1, W1.y);
            fma2(acc[1][2][0], a2, W1.x); fma2(acc[1][2][1], a2, W1.y);
            fma2(acc[1][3][0], a3, W1.x); fma2(acc[1][3][1], a3, W1.y);
        }
        if (kc < 3) cp_wait0();
        __syncthreads();
    }

    #pragma unroll
    for (int s = 0; s < 2; s++) {
        float* C = s ? C1 : C0;
        float4 bi = make_float4(0.f, 0.f, 0.f, 0.f);
        if (kh == 0) {
            const float* bias = (s ? b_t : b_h) + boff;
            bi = *(const float4*)(bias + col0 + cg * 4);
        }
        #pragma unroll
        for (int r = 0; r < 4; r++) {
            float2 p0 = unpack2(acc[s][r][0]);
            float2 p1 = unpack2(acc[s][r][1]);
            int row = row0 + rg * 4 + r;
            float4 o = make_float4(p0.x + bi.x, p0.y + bi.y, p1.x + bi.z, p1.y + bi.w);
            *(float4*)(C + ((size_t)b * rows + row) * DD + col0 + cg * 4) = o;
        }
    }
}

// ---------------- mid: uproj (256) + usum (16) + scores (128); sums K-split partials
__global__ __launch_bounds__(256) void k_mid(const float* __restrict__ W_h,
                                             const float* __restrict__ W_t)
{
    __shared__ __align__(16) char buf[33792];
    int blk = blockIdx.x;
    int tid = threadIdx.x;

    if (blk < 256) {
        int ct = blk & 1;
        int g = blk >> 1;
        int s = g >> 6, b = (g >> 3) & 7, h = g & 7;
        const float* Wo = (s ? W_t : W_h) + 3 * 65536 + h * DKK * DD;
        const float* V  = g_v[s]  + (size_t)b * MM * DD + h * DKK;
        const float* V2 = g_v2[s] + (size_t)b * MM * DD + h * DKK;
        int col0 = ct * 128;
        float (*a_sh)[132] = (float(*)[132])buf;
        float (*w_sh)[128] = (float(*)[128])(buf + 16896);

        #pragma unroll
        for (int i = 0; i < 4; i++) {
            int f = tid + i * 256;
            int r = f >> 3;
            int kq = (f & 7) * 4;
            float4 a0 = *(const float4*)(V  + (size_t)r * DD + kq);
            float4 a1 = *(const float4*)(V2 + (size_t)r * DD + kq);
            a_sh[kq+0][r] = a0.x + a1.x; a_sh[kq+1][r] = a0.y + a1.y;
            a_sh[kq+2][r] = a0.z + a1.z; a_sh[kq+3][r] = a0.w + a1.w;
        }
        #pragma unroll
        for (int i = 0; i < 4; i++) {
            int idx = tid + i * 256;
            int kk = idx >> 5;
            int dq = (idx & 31) * 4;
            *(float4*)&w_sh[kk][dq] = *(const float4*)(Wo + (size_t)kk * DD + col0 + dq);
        }
        __syncthreads();

        // WARP-UNIFORM map: A reads broadcast within warp halves
        int rg = tid >> 4;    // 16 row groups x 8 rows
        int cg = tid & 15;    // 16 col groups x 8 cols
        ull acc[4][8];
        #pragma unroll
        for (int p = 0; p < 4; p++)
            #pragma unroll
            for (int c = 0; c < 8; c++) acc[p][c] = 0ull;
        #pragma unroll
        for (int kk = 0; kk < 32; kk++) {
            ulonglong2 A0 = *(const ulonglong2*)&a_sh[kk][rg * 8];
            ulonglong2 A1 = *(const ulonglong2*)&a_sh[kk][rg * 8 + 4];
            float4 wa = *(const float4*)&w_sh[kk][cg * 8];
            float4 wb = *(const float4*)&w_sh[kk][cg * 8 + 4];
            ull wp[8] = { bcast2(wa.x), bcast2(wa.y), bcast2(wa.z), bcast2(wa.w),
                          bcast2(wb.x), bcast2(wb.y), bcast2(wb.z), bcast2(wb.w) };
            #pragma unroll
            for (int c = 0; c < 8; c++) {
                fma2(acc[0][c], A0.x, wp[c]);
                fma2(acc[1][c], A0.y, wp[c]);
                fma2(acc[2][c], A1.x, wp[c]);
                fma2(acc[3][c], A1.y, wp[c]);
            }
        }
        float* U = g_u[s] + ((size_t)(b * HH + h) * MM) * DD;
        #pragma unroll
        for (int p = 0; p < 4; p++) {
            float2 u0 = unpack2(acc[p][0]), u1 = unpack2(acc[p][1]);
            float2 u2 = unpack2(acc[p][2]), u3 = unpack2(acc[p][3]);
            float2 u4 = unpack2(acc[p][4]), u5 = unpack2(acc[p][5]);
            float2 u6 = unpack2(acc[p][6]), u7 = unpack2(acc[p][7]);
            int re = rg * 8 + 2 * p;
            float* d0 = U + (size_t)re * DD + col0 + cg * 8;
            float* d1 = d0 + DD;
            *(float4*)(d0)     = make_float4(u0.x, u1.x, u2.x, u3.x);
            *(float4*)(d0 + 4) = make_float4(u4.x, u5.x, u6.x, u7.x);
            *(float4*)(d1)     = make_float4(u0.y, u1.y, u2.y, u3.y);
            *(float4*)(d1 + 4) = make_float4(u4.y, u5.y, u6.y, u7.y);
        }
    } else if (blk < 272) {
        int id = blk - 256;
        int b = id & 7, s = id >> 3;
        const float* Wo = (s ? W_t : W_h) + 3 * 65536;
        float* vs = (float*)buf;
        int d = tid;
        const float* v  = g_v[s]  + (size_t)b * MM * DD;
        const float* v2 = g_v2[s] + (size_t)b * MM * DD;
        float sum = 0.f;
        for (int m = 0; m < MM; m++) sum += v[m * DD + d] + v2[m * DD + d];
        vs[d] = sum;
        __syncthreads();
        float o = 0.f;
        for (int k = 0; k < DD; k++) o = fmaf(vs[k], Wo[(size_t)k * DD + d], o);
        g_usum[s][b * DD + d] = o;
    } else {
        int t = blk - 272;
        int h = t & 7, b = (t >> 3) & 7, s = t >> 6;
        float (*qs)[DKK + 1] = (float(*)[DKK + 1])buf;
        float (*ks)[DKK + 1] = (float(*)[DKK + 1])(buf + EE * (DKK + 1) * 4);
        const float* q  = g_q[s]  + (size_t)b * EE * DD + h * DKK;
        const float* q2 = g_q2[s] + (size_t)b * EE * DD + h * DKK;
        const float* k  = g_k[s]  + (size_t)b * MM * DD + h * DKK;
        const float* k2 = g_k2[s] + (size_t)b * MM * DD + h * DKK;
        for (int i = tid; i < EE * DKK; i += 256) {
            int r = i >> 5, c = i & 31;
            qs[r][c] = q[r * DD + c] + q2[r * DD + c];
        }
        for (int i = tid; i < MM * DKK; i += 256) {
            int r = i >> 5, c = i & 31;
            ks[r][c] = k[r * DD + c] + k2[r * DD + c];
        }
        __syncthreads();
        int j = tid & 63;
        int m0 = tid >> 6;
        float* Sbase = g_S[s] + (size_t)(b * HH + h) * MM * EE;
        const float scale = 0.17677669529663687f;
        for (int m = m0; m < MM; m += 4) {
            float acc = 0.f;
            #pragma unroll
            for (int c = 0; c < DKK; c++) acc = fmaf(qs[j][c], ks[m][c], acc);
            Sbase[(size_t)m * EE + j] = acc * scale;
        }
    }
}

// -------- fused output (R12 j-split): online stats, u staged in smem ---------------
__global__ __launch_bounds__(256, 3) void k_out3(const float* __restrict__ b_h,
                                                 const float* __restrict__ b_t,
                                                 float* __restrict__ out)
{
    int i = blockIdx.x;
    int b = blockIdx.y;
    int z = blockIdx.z;
    int s = z >> 1;
    int j0 = (z & 1) * 32;
    const float* bo = (s ? b_t : b_h) + 3 * 256;
    float* outS = out + (size_t)s * SETHALF + (size_t)b * NPAIR * DD;
    int tid = threadIdx.x;
    int cnt = g_cnt[b * EE + i];

    if (cnt == 0) {
        const float* us = g_usum[s] + b * DD;
        for (int idx = tid; idx < 32 * 64; idx += 256) {
            int j = j0 + (idx >> 6);
            int q = idx & 63;
            float4 bo4 = *(const float4*)(bo + q * 4);
            float4 u4 = *(const float4*)(us + q * 4);
            float4 o = make_float4(bo4.x + u4.x * (1.0f/128.0f),
                                   bo4.y + u4.y * (1.0f/128.0f),
                                   bo4.z + u4.z * (1.0f/128.0f),
                                   bo4.w + u4.w * (1.0f/128.0f));
            int pair = (s == 0) ? (i * EE + j) : (j * EE + i);
            *(float4*)(outS + (size_t)pair * DD + q * 4) = o;
        }
        return;
    }

    __shared__ int lst[MM];
    __shared__ float mx[HH][32];
    __shared__ float rs[HH][32];
    __shared__ float wsh[HH][4][32];
    __shared__ float4 sU[HH][4][64];   // 32 KB

    for (int t = tid; t < cnt; t += 256) lst[t] = g_list[(b * EE + i) * MM + t];
    __syncthreads();

    const float* Sb = g_S[s] + (size_t)(b * HH) * MM * EE;

    // online softmax stats: one (h, jl) per thread
    {
        int h = tid >> 5;
        int jl = tid & 31;
        const float* Sh = Sb + (size_t)h * MM * EE + j0 + jl;
        float m_ = -1e30f, se = 0.f;
        for (int c = 0; c < cnt; c++) {
            float v = Sh[(size_t)lst[c] * EE];
            float nm = fmaxf(m_, v);
            se = se * __expf(m_ - nm) + __expf(v - nm);
            m_ = nm;
        }
        mx[h][jl] = m_;
        rs[h][jl] = 1.0f / se;
    }
    __syncthreads();

    int dq = tid & 63;
    int jg = tid >> 6;
    ull acc[8][2];
    #pragma unroll
    for (int jj = 0; jj < 8; jj++) { acc[jj][0] = 0ull; acc[jj][1] = 0ull; }

    const float* Ug = g_u[s] + (size_t)(b * HH) * MM * DD;

    for (int base = 0; base < cnt; base += 4) {
        int ce = min(4, cnt - base);
        #pragma unroll
        for (int rr = 0; rr < 8; rr++) {
            int t = tid + rr * 256;
            int h = t >> 8, c = (t >> 6) & 3, q = t & 63;
            if (c < ce)
                sU[h][c][q] = *(const float4*)(Ug + ((size_t)h * MM + lst[base + c]) * DD + q * 4);
        }
        for (int t = tid; t < HH * 4 * 32; t += 256) {
            int h = t >> 7, c = (t >> 5) & 3, jl = t & 31;
            if (c < ce) {
                float sv = Sb[((size_t)h * MM + lst[base + c]) * EE + j0 + jl];
                wsh[h][c][jl] = __expf(sv - mx[h][jl]) * rs[h][jl];
            }
        }
        __syncthreads();
        for (int c = 0; c < ce; c++) {
            #pragma unroll
            for (int h = 0; h < HH; h++) {
                ulonglong2 U = *(const ulonglong2*)&sU[h][c][dq];
                const float* wr = &wsh[h][c][jg * 8];
                float4 wa = *(const float4*)(wr);
                float4 wb = *(const float4*)(wr + 4);
                ull w0 = bcast2(wa.x), w1 = bcast2(wa.y), w2 = bcast2(wa.z), w3 = bcast2(wa.w);
                fma2(acc[0][0], w0, U.x); fma2(acc[0][1], w0, U.y);
                fma2(acc[1][0], w1, U.x); fma2(acc[1][1], w1, U.y);
                fma2(acc[2][0], w2, U.x); fma2(acc[2][1], w2, U.y);
                fma2(acc[3][0], w3, U.x); fma2(acc[3][1], w3, U.y);
                ull w4 = bcast2(wb.x), w5 = bcast2(wb.y), w6 = bcast2(wb.z), w7 = bcast2(wb.w);
                fma2(acc[4][0], w4, U.x); fma2(acc[4][1], w4, U.y);
                fma2(acc[5][0], w5, U.x); fma2(acc[5][1], w5, U.y);
                fma2(acc[6][0], w6, U.x); fma2(acc[6][1], w6, U.y);
                fma2(acc[7][0], w7, U.x); fma2(acc[7][1], w7, U.y);
            }
        }
        __syncthreads();
    }

    float4 bo4 = *(const float4*)(bo + dq * 4);
    #pragma unroll
    for (int jj = 0; jj < 8; jj++) {
        int j = j0 + jg * 8 + jj;
        int pair = (s == 0) ? (i * EE + j) : (j * EE + i);
        float2 p0 = unpack2(acc[jj][0]);
        float2 p1 = unpack2(acc[jj][1]);
        float4 o = make_float4(p0.x + bo4.x, p0.y + bo4.y, p1.x + bo4.z, p1.y + bo4.w);
        *(float4*)(outS + (size_t)pair * DD + dq * 4) = o;
    }
}

// ---------------- launch ----------------
extern "C" void kernel_launch(void* const* d_in, const int* in_sizes, int n_in,
                              void* d_out, int out_size) {
    const float* entities  = (const float*)d_in[0];
    const float* mentions  = (const float*)d_in[1];
    const float* sentences = (const float*)d_in[2];
    const int*   sent_ids  = (const int*)d_in[3];
    const int*   eid       = (const int*)d_in[4];
    const float* W_h       = (const float*)d_in[5];
    const float* b_h       = (const float*)d_in[6];
    const float* W_t       = (const float*)d_in[7];
    const float* b_t       = (const float*)d_in[8];
    float* out = (float*)d_out;

    k_gemm_all<<<dim3(8, 6, BB), 256>>>(entities, mentions, sentences, sent_ids, eid,
                                        W_h, b_h, W_t, b_t);
    k_mid<<<400, 256>>>(W_h, W_t);
    k_out3<<<dim3(EE, BB, 4), 256>>>(b_h, b_t, out);
}

// round 15
// speedup vs baseline: 1.0440x; 1.0049x over previous
#include <cuda_runtime.h>

#define BB 8
#define EE 64
#define MM 128
#define DD 256
#define HH 8
#define DKK 32
#define NPAIR (EE*EE)
#define SETHALF (BB*NPAIR*DD)

typedef unsigned long long ull;

// ---- packed fp32x2 helpers ----
__device__ __forceinline__ void fma2(ull &d, ull a, ull b) {
    asm("fma.rn.f32x2 %0, %1, %2, %0;" : "+l"(d) : "l"(a), "l"(b));
}
__device__ __forceinline__ ull bcast2(float x) {
    ull d;
    asm("mov.b64 %0, {%1, %1};" : "=l"(d) : "r"(__float_as_uint(x)));
    return d;
}
__device__ __forceinline__ float2 unpack2(ull v) {
    float2 r;
    asm("mov.b64 {%0, %1}, %2;" : "=f"(r.x), "=f"(r.y) : "l"(v));
    return r;
}
// ---- cp.async ----
__device__ __forceinline__ void cp_async16(unsigned dst, const void* src) {
    asm volatile("cp.async.cg.shared.global [%0], [%1], 16;" :: "r"(dst), "l"(src));
}
__device__ __forceinline__ void cp_commit() { asm volatile("cp.async.commit_group;"); }
__device__ __forceinline__ void cp_wait0()  { asm volatile("cp.async.wait_group 0;" ::: "memory"); }

// ---------------- scratch ----------------
__device__ float g_q[2][BB*EE*DD];
__device__ float g_k[2][BB*MM*DD];
__device__ float g_v[2][BB*MM*DD];
__device__ float g_qp[3][2][BB*EE*DD];   // K-split partials kh=1..3
__device__ float g_kp[3][2][BB*MM*DD];
__device__ float g_vp[3][2][BB*MM*DD];
__device__ float g_u[2][BB*HH*MM*DD];
__device__ float g_S[2][BB*HH*MM*EE];    // [s][b][h][m][j], j innermost
__device__ float g_usum[2][BB*DD];
__device__ int   g_cnt[BB*EE];
__device__ int   g_list[BB*EE*MM];

// ---- merged projections; 4-way K-split, 3 blocks/SM, uniform grid ----
// grid (16, 5, 8): x = colTile(0..3) + kh(0..3)*4; y = job/rowTile.
__global__ __launch_bounds__(256, 3) void k_gemm_all(
    const float* __restrict__ entities, const float* __restrict__ mentions,
    const float* __restrict__ sentences, const int* __restrict__ sent_ids,
    const float* __restrict__ W_h, const float* __restrict__ b_h,
    const float* __restrict__ W_t, const float* __restrict__ b_t)
{
    __shared__ float a_sh[2][32][68];
    __shared__ float w_sh[2][2][32][64];
    int b = blockIdx.z;
    int y = blockIdx.y;
    int x = blockIdx.x;
    int colTile = x & 3;
    int kh = x >> 2;
    int tid = threadIdx.x;

    int job, rowTile;
    if (y == 0) { job = 0; rowTile = 0; }
    else if (y <= 2) { job = 1; rowTile = y - 1; }
    else { job = 2; rowTile = y - 3; }
    const float* A; int rows, woff, boff;
    float *C0, *C1;
    bool indirect = false;
    switch (job) {
      case 0:
        A = entities; rows = EE;  woff = 0;      boff = 0;
        C0 = kh ? g_qp[kh-1][0] : g_q[0]; C1 = kh ? g_qp[kh-1][1] : g_q[1]; break;
      case 1:
        A = nullptr;  rows = MM;  woff = 65536;  boff = 256; indirect = true;
        C0 = kh ? g_kp[kh-1][0] : g_k[0]; C1 = kh ? g_kp[kh-1][1] : g_k[1]; break;
      default:
        A = mentions; rows = MM;  woff = 131072; boff = 512;
        C0 = kh ? g_vp[kh-1][0] : g_v[0]; C1 = kh ? g_vp[kh-1][1] : g_v[1]; break;
    }
    int row0 = rowTile * 64;
    int col0 = colTile * 64;
    int kbase = kh * 64;

    int kqI[2], cI[2];
    const float* rp[2];
    #pragma unroll
    for (int i = 0; i < 2; i++) {
        int f = tid * 2 + i;
        int r = f >> 3;
        kqI[i] = (f & 7) * 4;
        cI[i]  = r ^ (((kqI[i] >> 3) & 3) << 3);
        if (indirect) {
            int sid = sent_ids[b * MM + row0 + r];
            rp[i] = sentences + ((size_t)(b * 32 + sid)) * DD + kbase + kqI[i];
        } else {
            rp[i] = A + ((size_t)b * rows + row0 + r) * DD + kbase + kqI[i];
        }
    }
    unsigned wbase = (unsigned)__cvta_generic_to_shared(&w_sh[0][0][0][0]);
    const unsigned WBUF = 2u * 32u * 64u * 4u;
    unsigned wdst[4];
    const float* wp[4];
    #pragma unroll
    for (int j = 0; j < 4; j++) {
        int idx = tid + j * 256;
        int ws = idx >> 9;
        int rem = idx & 511;
        int wk = rem >> 4;
        int wd = (rem & 15) * 4;
        wdst[j] = wbase + (unsigned)(((ws * 32 + wk) * 64 + wd) * 4);
        const float* Wsel = (ws ? W_t : W_h) + woff;
        wp[j] = Wsel + (size_t)(kbase + wk) * DD + col0 + wd;
    }

    int rg = tid >> 4;    // 16 row groups x 4 rows (warp-uniform)
    int cg = tid & 15;    // 16 col groups x 4 cols
    int rb = rg * 4;
    ull acc[2][4][2];     // [set][row][colpair]
    #pragma unroll
    for (int s = 0; s < 2; s++)
        #pragma unroll
        for (int r = 0; r < 4; r++)
            { acc[s][r][0] = 0ull; acc[s][r][1] = 0ull; }

    #pragma unroll
    for (int j = 0; j < 4; j++) cp_async16(wdst[j], wp[j]);
    cp_commit();
    {
        float4 pa0 = *(const float4*)(rp[0]);
        float4 pa1 = *(const float4*)(rp[1]);
        a_sh[0][kqI[0]+0][cI[0]] = pa0.x; a_sh[0][kqI[0]+1][cI[0]] = pa0.y;
        a_sh[0][kqI[0]+2][cI[0]] = pa0.z; a_sh[0][kqI[0]+3][cI[0]] = pa0.w;
        a_sh[0][kqI[1]+0][cI[1]] = pa1.x; a_sh[0][kqI[1]+1][cI[1]] = pa1.y;
        a_sh[0][kqI[1]+2][cI[1]] = pa1.z; a_sh[0][kqI[1]+3][cI[1]] = pa1.w;
    }
    cp_wait0();
    __syncthreads();

    float4 pa[2];
    #pragma unroll
    for (int kc = 0; kc < 2; kc++) {
        int buf = kc & 1;
        int nb = buf ^ 1;
        if (kc < 1) {
            int k0n = 32;
            #pragma unroll
            for (int j = 0; j < 4; j++)
                cp_async16(wdst[j] + (unsigned)nb * WBUF, wp[j] + (size_t)k0n * DD);
            cp_commit();
            #pragma unroll
            for (int i = 0; i < 2; i++) pa[i] = *(const float4*)(rp[i] + k0n);
        }
        #pragma unroll
        for (int kk = 0; kk < 24; kk++) {
            int cs = rb ^ (((kk >> 3) & 3) << 3);
            float4 Af = *(const float4*)&a_sh[buf][kk][cs];
            ulonglong2 W0 = *(const ulonglong2*)&w_sh[buf][0][kk][cg * 4];
            ulonglong2 W1 = *(const ulonglong2*)&w_sh[buf][1][kk][cg * 4];
            ull a0 = bcast2(Af.x), a1 = bcast2(Af.y), a2 = bcast2(Af.z), a3 = bcast2(Af.w);
            fma2(acc[0][0][0], a0, W0.x); fma2(acc[0][0][1], a0, W0.y);
            fma2(acc[0][1][0], a1, W0.x); fma2(acc[0][1][1], a1, W0.y);
            fma2(acc[0][2][0], a2, W0.x); fma2(acc[0][2][1], a2, W0.y);
            fma2(acc[0][3][0], a3, W0.x); fma2(acc[0][3][1], a3, W0.y);
            fma2(acc[1][0][0], a0, W1.x); fma2(acc[1][0][1], a0, W1.y);
            fma2(acc[1][1][0], a1, W1.x); fma2(acc[1][1][1], a1, W1.y);
            fma2(acc[1][2][0], a2, W1.x); fma2(acc[1][2][1], a2, W1.y);
            fma2(acc[1][3][0], a3, W1.x); fma2(acc[1][3][1], a3, W1.y);
        }
        if (kc < 1) {
            #pragma unroll
            for (int i = 0; i < 2; i++) {
                a_sh[nb][kqI[i]+0][cI[i]] = pa[i].x; a_sh[nb][kqI[i]+1][cI[i]] = pa[i].y;
                a_sh[nb][kqI[i]+2][cI[i]] = pa[i].z; a_sh[nb][kqI[i]+3][cI[i]] = pa[i].w;
            }
        }
        #pragma unroll
        for (int kk = 24; kk < 32; kk++) {
            int cs = rb ^ (((kk >> 3) & 3) << 3);
            float4 Af = *(const float4*)&a_sh[buf][kk][cs];
            ulonglong2 W0 = *(const ulonglong2*)&w_sh[buf][0][kk][cg * 4];
            ulonglong2 W1 = *(const ulonglong2*)&w_sh[buf][1][kk][cg * 4];
            ull a0 = bcast2(Af.x), a1 = bcast2(Af.y), a2 = bcast2(Af.z), a3 = bcast2(Af.w);
            fma2(acc[0][0][0], a0, W0.x); fma2(acc[0][0][1], a0, W0.y);
            fma2(acc[0][1][0], a1, W0.x); fma2(acc[0][1][1], a1, W0.y);
            fma2(acc[0][2][0], a2, W0.x); fma2(acc[0][2][1], a2, W0.y);
            fma2(acc[0][3][0], a3, W0.x); fma2(acc[0][3][1], a3, W0.y);
            fma2(acc[1][0][0], a0, W1.x); fma2(acc[1][0][1], a0, W1.y);
            fma2(acc[1][1][0], a1, W1.x); fma2(acc[1][1][1], a1, W1.y);
            fma2(acc[1][2][0], a2, W1.x); fma2(acc[1][2][1], a2, W1.y);
            fma2(acc[1][3][0], a3, W1.x); fma2(acc[1][3][1], a3, W1.y);
        }
        if (kc < 1) cp_wait0();
        __syncthreads();
    }

    #pragma unroll
    for (int s = 0; s < 2; s++) {
        float* C = s ? C1 : C0;
        float4 bi = make_float4(0.f, 0.f, 0.f, 0.f);
        if (kh == 0) {
            const float* bias = (s ? b_t : b_h) + boff;
            bi = *(const float4*)(bias + col0 + cg * 4);
        }
        #pragma unroll
        for (int r = 0; r < 4; r++) {
            float2 p0 = unpack2(acc[s][r][0]);
            float2 p1 = unpack2(acc[s][r][1]);
            int row = row0 + rg * 4 + r;
            float4 o = make_float4(p0.x + bi.x, p0.y + bi.y, p1.x + bi.z, p1.y + bi.w);
            *(float4*)(C + ((size_t)b * rows + row) * DD + col0 + cg * 4) = o;
        }
    }
}

// ---- mid: uproj (256) + usum (16) + scores (128) + lists (8); sums 4 partials ----
__global__ __launch_bounds__(256) void k_mid(const float* __restrict__ W_h,
                                             const float* __restrict__ W_t,
                                             const int* __restrict__ eid)
{
    __shared__ __align__(16) char buf[33792];
    int blk = blockIdx.x;
    int tid = threadIdx.x;

    if (blk < 256) {
        int ct = blk & 1;
        int g = blk >> 1;
        int s = g >> 6, b = (g >> 3) & 7, h = g & 7;
        const float* Wo = (s ? W_t : W_h) + 3 * 65536 + h * DKK * DD;
        size_t voff = (size_t)b * MM * DD + h * DKK;
        const float* V  = g_v[s] + voff;
        const float* P0 = g_vp[0][s] + voff;
        const float* P1 = g_vp[1][s] + voff;
        const float* P2 = g_vp[2][s] + voff;
        int col0 = ct * 128;
        float (*a_sh)[132] = (float(*)[132])buf;
        float (*w_sh)[128] = (float(*)[128])(buf + 16896);

        #pragma unroll
        for (int i = 0; i < 4; i++) {
            int f = tid + i * 256;
            int r = f >> 3;
            int kq = (f & 7) * 4;
            size_t o = (size_t)r * DD + kq;
            float4 a0 = *(const float4*)(V + o);
            float4 a1 = *(const float4*)(P0 + o);
            float4 a2 = *(const float4*)(P1 + o);
            float4 a3 = *(const float4*)(P2 + o);
            a_sh[kq+0][r] = a0.x + a1.x + a2.x + a3.x;
            a_sh[kq+1][r] = a0.y + a1.y + a2.y + a3.y;
            a_sh[kq+2][r] = a0.z + a1.z + a2.z + a3.z;
            a_sh[kq+3][r] = a0.w + a1.w + a2.w + a3.w;
        }
        #pragma unroll
        for (int i = 0; i < 4; i++) {
            int idx = tid + i * 256;
            int kk = idx >> 5;
            int dq = (idx & 31) * 4;
            *(float4*)&w_sh[kk][dq] = *(const float4*)(Wo + (size_t)kk * DD + col0 + dq);
        }
        __syncthreads();

        int rg = tid >> 4;
        int cg = tid & 15;
        ull acc[4][8];
        #pragma unroll
        for (int p = 0; p < 4; p++)
            #pragma unroll
            for (int c = 0; c < 8; c++) acc[p][c] = 0ull;
        #pragma unroll
        for (int kk = 0; kk < 32; kk++) {
            ulonglong2 A0 = *(const ulonglong2*)&a_sh[kk][rg * 8];
            ulonglong2 A1 = *(const ulonglong2*)&a_sh[kk][rg * 8 + 4];
            float4 wa = *(const float4*)&w_sh[kk][cg * 8];
            float4 wb = *(const float4*)&w_sh[kk][cg * 8 + 4];
            ull wp[8] = { bcast2(wa.x), bcast2(wa.y), bcast2(wa.z), bcast2(wa.w),
                          bcast2(wb.x), bcast2(wb.y), bcast2(wb.z), bcast2(wb.w) };
            #pragma unroll
            for (int c = 0; c < 8; c++) {
                fma2(acc[0][c], A0.x, wp[c]);
                fma2(acc[1][c], A0.y, wp[c]);
                fma2(acc[2][c], A1.x, wp[c]);
                fma2(acc[3][c], A1.y, wp[c]);
            }
        }
        float* U = g_u[s] + ((size_t)(b * HH + h) * MM) * DD;
        #pragma unroll
        for (int p = 0; p < 4; p++) {
            float2 u0 = unpack2(acc[p][0]), u1 = unpack2(acc[p][1]);
            float2 u2 = unpack2(acc[p][2]), u3 = unpack2(acc[p][3]);
            float2 u4 = unpack2(acc[p][4]), u5 = unpack2(acc[p][5]);
            float2 u6 = unpack2(acc[p][6]), u7 = unpack2(acc[p][7]);
            int re = rg * 8 + 2 * p;
            float* d0 = U + (size_t)re * DD + col0 + cg * 8;
            float* d1 = d0 + DD;
            *(float4*)(d0)     = make_float4(u0.x, u1.x, u2.x, u3.x);
            *(float4*)(d0 + 4) = make_float4(u4.x, u5.x, u6.x, u7.x);
            *(float4*)(d1)     = make_float4(u0.y, u1.y, u2.y, u3.y);
            *(float4*)(d1 + 4) = make_float4(u4.y, u5.y, u6.y, u7.y);
        }
    } else if (blk < 272) {
        int id = blk - 256;
        int b = id & 7, s = id >> 3;
        const float* Wo = (s ? W_t : W_h) + 3 * 65536;
        float* vs = (float*)buf;
        int d = tid;
        size_t voff = (size_t)b * MM * DD;
        const float* v  = g_v[s] + voff;
        const float* p0 = g_vp[0][s] + voff;
        const float* p1 = g_vp[1][s] + voff;
        const float* p2 = g_vp[2][s] + voff;
        float sum = 0.f;
        for (int m = 0; m < MM; m++) {
            size_t o = (size_t)m * DD + d;
            sum += v[o] + p0[o] + p1[o] + p2[o];
        }
        vs[d] = sum;
        __syncthreads();
        float o = 0.f;
        for (int k = 0; k < DD; k++) o = fmaf(vs[k], Wo[(size_t)k * DD + d], o);
        g_usum[s][b * DD + d] = o;
    } else if (blk < 400) {
        int t = blk - 272;
        int h = t & 7, b = (t >> 3) & 7, s = t >> 6;
        float (*qs)[DKK + 1] = (float(*)[DKK + 1])buf;
        float (*ks)[DKK + 1] = (float(*)[DKK + 1])(buf + EE * (DKK + 1) * 4);
        size_t qoff = (size_t)b * EE * DD + h * DKK;
        size_t koff = (size_t)b * MM * DD + h * DKK;
        const float* q  = g_q[s] + qoff;
        const float* q0 = g_qp[0][s] + qoff;
        const float* q1 = g_qp[1][s] + qoff;
        const float* q2 = g_qp[2][s] + qoff;
        const float* k  = g_k[s] + koff;
        const float* k0 = g_kp[0][s] + koff;
        const float* k1 = g_kp[1][s] + koff;
        const float* k2 = g_kp[2][s] + koff;
        for (int i = tid; i < EE * DKK; i += 256) {
            int r = i >> 5, c = i & 31;
            size_t o = (size_t)r * DD + c;
            qs[r][c] = q[o] + q0[o] + q1[o] + q2[o];
        }
        for (int i = tid; i < MM * DKK; i += 256) {
            int r = i >> 5, c = i & 31;
            size_t o = (size_t)r * DD + c;
            ks[r][c] = k[o] + k0[o] + k1[o] + k2[o];
        }
        __syncthreads();
        int j = tid & 63;
        int m0 = tid >> 6;
        float* Sbase = g_S[s] + (size_t)(b * HH + h) * MM * EE;
        const float scale = 0.17677669529663687f;
        for (int m = m0; m < MM; m += 4) {
            float acc = 0.f;
            #pragma unroll
            for (int c = 0; c < DKK; c++) acc = fmaf(qs[j][c], ks[m][c], acc);
            Sbase[(size_t)m * EE + j] = acc * scale;
        }
    } else {
        // list building (depends only on eid)
        int b = blk - 400;
        if (tid < EE) {
            int e = tid;
            int cnt = 0;
            for (int m = 0; m < MM; m++)
                if (eid[b*MM + m] == e) g_list[(b*EE + e)*MM + cnt++] = m;
            g_cnt[b*EE + e] = cnt;
        }
    }
}

// -------- fused output (j-split): online stats, u staged in smem ---------------
__global__ __launch_bounds__(256, 3) void k_out3(const float* __restrict__ b_h,
                                                 const float* __restrict__ b_t,
                                                 float* __restrict__ out)
{
    int i = blockIdx.x;
    int b = blockIdx.y;
    int z = blockIdx.z;
    int s = z >> 1;
    int j0 = (z & 1) * 32;
    const float* bo = (s ? b_t : b_h) + 3 * 256;
    float* outS = out + (size_t)s * SETHALF + (size_t)b * NPAIR * DD;
    int tid = threadIdx.x;
    int cnt = g_cnt[b * EE + i];

    if (cnt == 0) {
        const float* us = g_usum[s] + b * DD;
        for (int idx = tid; idx < 32 * 64; idx += 256) {
            int j = j0 + (idx >> 6);
            int q = idx & 63;
            float4 bo4 = *(const float4*)(bo + q * 4);
            float4 u4 = *(const float4*)(us + q * 4);
            float4 o = make_float4(bo4.x + u4.x * (1.0f/128.0f),
                                   bo4.y + u4.y * (1.0f/128.0f),
                                   bo4.z + u4.z * (1.0f/128.0f),
                                   bo4.w + u4.w * (1.0f/128.0f));
            int pair = (s == 0) ? (i * EE + j) : (j * EE + i);
            *(float4*)(outS + (size_t)pair * DD + q * 4) = o;
        }
        return;
    }

    __shared__ int lst[MM];
    __shared__ float mx[HH][32];
    __shared__ float rs[HH][32];
    __shared__ float wsh[HH][4][32];
    __shared__ float4 sU[HH][4][64];   // 32 KB

    for (int t = tid; t < cnt; t += 256) lst[t] = g_list[(b * EE + i) * MM + t];
    __syncthreads();

    const float* Sb = g_S[s] + (size_t)(b * HH) * MM * EE;

    {
        int h = tid >> 5;
        int jl = tid & 31;
        const float* Sh = Sb + (size_t)h * MM * EE + j0 + jl;
        float m_ = -1e30f, se = 0.f;
        for (int c = 0; c < cnt; c++) {
            float v = Sh[(size_t)lst[c] * EE];
            float nm = fmaxf(m_, v);
            se = se * __expf(m_ - nm) + __expf(v - nm);
            m_ = nm;
        }
        mx[h][jl] = m_;
        rs[h][jl] = 1.0f / se;
    }
    __syncthreads();

    int dq = tid & 63;
    int jg = tid >> 6;
    ull acc[8][2];
    #pragma unroll
    for (int jj = 0; jj < 8; jj++) { acc[jj][0] = 0ull; acc[jj][1] = 0ull; }

    const float* Ug = g_u[s] + (size_t)(b * HH) * MM * DD;

    for (int base = 0; base < cnt; base += 4) {
        int ce = min(4, cnt - base);
        #pragma unroll
        for (int rr = 0; rr < 8; rr++) {
            int t = tid + rr * 256;
            int h = t >> 8, c = (t >> 6) & 3, q = t & 63;
            if (c < ce)
                sU[h][c][q] = *(const float4*)(Ug + ((size_t)h * MM + lst[base + c]) * DD + q * 4);
        }
        for (int t = tid; t < HH * 4 * 32; t += 256) {
            int h = t >> 7, c = (t >> 5) & 3, jl = t & 31;
            if (c < ce) {
                float sv = Sb[((size_t)h * MM + lst[base + c]) * EE + j0 + jl];
                wsh[h][c][jl] = __expf(sv - mx[h][jl]) * rs[h][jl];
            }
        }
        __syncthreads();
        for (int c = 0; c < ce; c++) {
            #pragma unroll
            for (int h = 0; h < HH; h++) {
                ulonglong2 U = *(const ulonglong2*)&sU[h][c][dq];
                const float* wr = &wsh[h][c][jg * 8];
                float4 wa = *(const float4*)(wr);
                float4 wb = *(const float4*)(wr + 4);
                ull w0 = bcast2(wa.x), w1 = bcast2(wa.y), w2 = bcast2(wa.z), w3 = bcast2(wa.w);
                fma2(acc[0][0], w0, U.x); fma2(acc[0][1], w0, U.y);
                fma2(acc[1][0], w1, U.x); fma2(acc[1][1], w1, U.y);
                fma2(acc[2][0], w2, U.x); fma2(acc[2][1], w2, U.y);
                fma2(acc[3][0], w3, U.x); fma2(acc[3][1], w3, U.y);
                ull w4 = bcast2(wb.x), w5 = bcast2(wb.y), w6 = bcast2(wb.z), w7 = bcast2(wb.w);
                fma2(acc[4][0], w4, U.x); fma2(acc[4][1], w4, U.y);
                fma2(acc[5][0], w5, U.x); fma2(acc[5][1], w5, U.y);
                fma2(acc[6][0], w6, U.x); fma2(acc[6][1], w6, U.y);
                fma2(acc[7][0], w7, U.x); fma2(acc[7][1], w7, U.y);
            }
        }
        __syncthreads();
    }

    float4 bo4 = *(const float4*)(bo + dq * 4);
    #pragma unroll
    for (int jj = 0; jj < 8; jj++) {
        int j = j0 + jg * 8 + jj;
        int pair = (s == 0) ? (i * EE + j) : (j * EE + i);
        float2 p0 = unpack2(acc[jj][0]);
        float2 p1 = unpack2(acc[jj][1]);
        float4 o = make_float4(p0.x + bo4.x, p0.y + bo4.y, p1.x + bo4.z, p1.y + bo4.w);
        *(float4*)(outS + (size_t)pair * DD + dq * 4) = o;
    }
}

// ---------------- launch ----------------
extern "C" void kernel_launch(void* const* d_in, const int* in_sizes, int n_in,
                              void* d_out, int out_size) {
    const float* entities  = (const float*)d_in[0];
    const float* mentions  = (const float*)d_in[1];
    const float* sentences = (const float*)d_in[2];
    const int*   sent_ids  = (const int*)d_in[3];
    const int*   eid       = (const int*)d_in[4];
    const float* W_h       = (const float*)d_in[5];
    const float* b_h       = (const float*)d_in[6];
    const float* W_t       = (const float*)d_in[7];
    const float* b_t       = (const float*)d_in[8];
    float* out = (float*)d_out;

    k_gemm_all<<<dim3(16, 5, BB), 256>>>(entities, mentions, sentences, sent_ids,
                                         W_h, b_h, W_t, b_t);
    k_mid<<<408, 256>>>(W_h, W_t, eid);
    k_out3<<<dim3(EE, BB, 4), 256>>>(b_h, b_t, out);
}

// round 16
// speedup vs baseline: 1.0470x; 1.0029x over previous
#include <cuda_runtime.h>

#define BB 8
#define EE 64
#define MM 128
#define DD 256
#define HH 8
#define DKK 32
#define NPAIR (EE*EE)
#define SETHALF (BB*NPAIR*DD)

typedef unsigned long long ull;

// ---- packed fp32x2 helpers ----
__device__ __forceinline__ void fma2(ull &d, ull a, ull b) {
    asm("fma.rn.f32x2 %0, %1, %2, %0;" : "+l"(d) : "l"(a), "l"(b));
}
__device__ __forceinline__ ull bcast2(float x) {
    ull d;
    asm("mov.b64 %0, {%1, %1};" : "=l"(d) : "r"(__float_as_uint(x)));
    return d;
}
__device__ __forceinline__ float2 unpack2(ull v) {
    float2 r;
    asm("mov.b64 {%0, %1}, %2;" : "=f"(r.x), "=f"(r.y) : "l"(v));
    return r;
}
// ---- cp.async ----
__device__ __forceinline__ void cp_async16(unsigned dst, const void* src) {
    asm volatile("cp.async.cg.shared.global [%0], [%1], 16;" :: "r"(dst), "l"(src));
}
__device__ __forceinline__ void cp_commit() { asm volatile("cp.async.commit_group;"); }
__device__ __forceinline__ void cp_wait0()  { asm volatile("cp.async.wait_group 0;" ::: "memory"); }

// ---------------- scratch ----------------
__device__ float g_q[2][BB*EE*DD];
__device__ float g_k[2][BB*MM*DD];
__device__ float g_v[2][BB*MM*DD];
__device__ float g_qp[3][2][BB*EE*DD];   // K-split partials kh=1..3
__device__ float g_kp[3][2][BB*MM*DD];
__device__ float g_vp[3][2][BB*MM*DD];
__device__ float g_u[2][BB*HH*MM*DD];
__device__ float g_S[2][BB*HH*MM*EE];    // [s][b][h][m][j], j innermost
__device__ float g_usum[2][BB*DD];
__device__ int   g_cnt[BB*EE];
__device__ int   g_list[BB*EE*MM];

// ---- merged projections; 4-way K-split, 3 blocks/SM, uniform grid ----
// grid (16, 5, 8): x = colTile(0..3) + kh(0..3)*4; y = job/rowTile.
__global__ __launch_bounds__(256, 3) void k_gemm_all(
    const float* __restrict__ entities, const float* __restrict__ mentions,
    const float* __restrict__ sentences, const int* __restrict__ sent_ids,
    const float* __restrict__ W_h, const float* __restrict__ b_h,
    const float* __restrict__ W_t, const float* __restrict__ b_t)
{
    __shared__ float a_sh[2][32][68];
    __shared__ float w_sh[2][2][32][64];
    int b = blockIdx.z;
    int y = blockIdx.y;
    int x = blockIdx.x;
    int colTile = x & 3;
    int kh = x >> 2;
    int tid = threadIdx.x;

    int job, rowTile;
    if (y == 0) { job = 0; rowTile = 0; }
    else if (y <= 2) { job = 1; rowTile = y - 1; }
    else { job = 2; rowTile = y - 3; }
    const float* A; int rows, woff, boff;
    float *C0, *C1;
    bool indirect = false;
    switch (job) {
      case 0:
        A = entities; rows = EE;  woff = 0;      boff = 0;
        C0 = kh ? g_qp[kh-1][0] : g_q[0]; C1 = kh ? g_qp[kh-1][1] : g_q[1]; break;
      case 1:
        A = nullptr;  rows = MM;  woff = 65536;  boff = 256; indirect = true;
        C0 = kh ? g_kp[kh-1][0] : g_k[0]; C1 = kh ? g_kp[kh-1][1] : g_k[1]; break;
      default:
        A = mentions; rows = MM;  woff = 131072; boff = 512;
        C0 = kh ? g_vp[kh-1][0] : g_v[0]; C1 = kh ? g_vp[kh-1][1] : g_v[1]; break;
    }
    int row0 = rowTile * 64;
    int col0 = colTile * 64;
    int kbase = kh * 64;

    int kqI[2], cI[2];
    const float* rp[2];
    #pragma unroll
    for (int i = 0; i < 2; i++) {
        int f = tid * 2 + i;
        int r = f >> 3;
        kqI[i] = (f & 7) * 4;
        cI[i]  = r ^ (((kqI[i] >> 3) & 3) << 3);
        if (indirect) {
            int sid = sent_ids[b * MM + row0 + r];
            rp[i] = sentences + ((size_t)(b * 32 + sid)) * DD + kbase + kqI[i];
        } else {
            rp[i] = A + ((size_t)b * rows + row0 + r) * DD + kbase + kqI[i];
        }
    }
    unsigned wbase = (unsigned)__cvta_generic_to_shared(&w_sh[0][0][0][0]);
    const unsigned WBUF = 2u * 32u * 64u * 4u;
    unsigned wdst[4];
    const float* wp[4];
    #pragma unroll
    for (int j = 0; j < 4; j++) {
        int idx = tid + j * 256;
        int ws = idx >> 9;
        int rem = idx & 511;
        int wk = rem >> 4;
        int wd = (rem & 15) * 4;
        wdst[j] = wbase + (unsigned)(((ws * 32 + wk) * 64 + wd) * 4);
        const float* Wsel = (ws ? W_t : W_h) + woff;
        wp[j] = Wsel + (size_t)(kbase + wk) * DD + col0 + wd;
    }

    int rg = tid >> 4;
    int cg = tid & 15;
    int rb = rg * 4;
    ull acc[2][4][2];
    #pragma unroll
    for (int s = 0; s < 2; s++)
        #pragma unroll
        for (int r = 0; r < 4; r++)
            { acc[s][r][0] = 0ull; acc[s][r][1] = 0ull; }

    #pragma unroll
    for (int j = 0; j < 4; j++) cp_async16(wdst[j], wp[j]);
    cp_commit();
    {
        float4 pa0 = *(const float4*)(rp[0]);
        float4 pa1 = *(const float4*)(rp[1]);
        a_sh[0][kqI[0]+0][cI[0]] = pa0.x; a_sh[0][kqI[0]+1][cI[0]] = pa0.y;
        a_sh[0][kqI[0]+2][cI[0]] = pa0.z; a_sh[0][kqI[0]+3][cI[0]] = pa0.w;
        a_sh[0][kqI[1]+0][cI[1]] = pa1.x; a_sh[0][kqI[1]+1][cI[1]] = pa1.y;
        a_sh[0][kqI[1]+2][cI[1]] = pa1.z; a_sh[0][kqI[1]+3][cI[1]] = pa1.w;
    }
    cp_wait0();
    __syncthreads();

    float4 pa[2];
    #pragma unroll
    for (int kc = 0; kc < 2; kc++) {
        int buf = kc & 1;
        int nb = buf ^ 1;
        if (kc < 1) {
            int k0n = 32;
            #pragma unroll
            for (int j = 0; j < 4; j++)
                cp_async16(wdst[j] + (unsigned)nb * WBUF, wp[j] + (size_t)k0n * DD);
            cp_commit();
            #pragma unroll
            for (int i = 0; i < 2; i++) pa[i] = *(const float4*)(rp[i] + k0n);
        }
        #pragma unroll
        for (int kk = 0; kk < 24; kk++) {
            int cs = rb ^ (((kk >> 3) & 3) << 3);
            float4 Af = *(const float4*)&a_sh[buf][kk][cs];
            ulonglong2 W0 = *(const ulonglong2*)&w_sh[buf][0][kk][cg * 4];
            ulonglong2 W1 = *(const ulonglong2*)&w_sh[buf][1][kk][cg * 4];
            ull a0 = bcast2(Af.x), a1 = bcast2(Af.y), a2 = bcast2(Af.z), a3 = bcast2(Af.w);
            fma2(acc[0][0][0], a0, W0.x); fma2(acc[0][0][1], a0, W0.y);
            fma2(acc[0][1][0], a1, W0.x); fma2(acc[0][1][1], a1, W0.y);
            fma2(acc[0][2][0], a2, W0.x); fma2(acc[0][2][1], a2, W0.y);
            fma2(acc[0][3][0], a3, W0.x); fma2(acc[0][3][1], a3, W0.y);
            fma2(acc[1][0][0], a0, W1.x); fma2(acc[1][0][1], a0, W1.y);
            fma2(acc[1][1][0], a1, W1.x); fma2(acc[1][1][1], a1, W1.y);
            fma2(acc[1][2][0], a2, W1.x); fma2(acc[1][2][1], a2, W1.y);
            fma2(acc[1][3][0], a3, W1.x); fma2(acc[1][3][1], a3, W1.y);
        }
        if (kc < 1) {
            #pragma unroll
            for (int i = 0; i < 2; i++) {
                a_sh[nb][kqI[i]+0][cI[i]] = pa[i].x; a_sh[nb][kqI[i]+1][cI[i]] = pa[i].y;
                a_sh[nb][kqI[i]+2][cI[i]] = pa[i].z; a_sh[nb][kqI[i]+3][cI[i]] = pa[i].w;
            }
        }
        #pragma unroll
        for (int kk = 24; kk < 32; kk++) {
            int cs = rb ^ (((kk >> 3) & 3) << 3);
            float4 Af = *(const float4*)&a_sh[buf][kk][cs];
            ulonglong2 W0 = *(const ulonglong2*)&w_sh[buf][0][kk][cg * 4];
            ulonglong2 W1 = *(const ulonglong2*)&w_sh[buf][1][kk][cg * 4];
            ull a0 = bcast2(Af.x), a1 = bcast2(Af.y), a2 = bcast2(Af.z), a3 = bcast2(Af.w);
            fma2(acc[0][0][0], a0, W0.x); fma2(acc[0][0][1], a0, W0.y);
            fma2(acc[0][1][0], a1, W0.x); fma2(acc[0][1][1], a1, W0.y);
            fma2(acc[0][2][0], a2, W0.x); fma2(acc[0][2][1], a2, W0.y);
            fma2(acc[0][3][0], a3, W0.x); fma2(acc[0][3][1], a3, W0.y);
            fma2(acc[1][0][0], a0, W1.x); fma2(acc[1][0][1], a0, W1.y);
            fma2(acc[1][1][0], a1, W1.x); fma2(acc[1][1][1], a1, W1.y);
            fma2(acc[1][2][0], a2, W1.x); fma2(acc[1][2][1], a2, W1.y);
            fma2(acc[1][3][0], a3, W1.x); fma2(acc[1][3][1], a3, W1.y);
        }
        if (kc < 1) cp_wait0();
        __syncthreads();
    }

    #pragma unroll
    for (int s = 0; s < 2; s++) {
        float* C = s ? C1 : C0;
        float4 bi = make_float4(0.f, 0.f, 0.f, 0.f);
        if (kh == 0) {
            const float* bias = (s ? b_t : b_h) + boff;
            bi = *(const float4*)(bias + col0 + cg * 4);
        }
        #pragma unroll
        for (int r = 0; r < 4; r++) {
            float2 p0 = unpack2(acc[s][r][0]);
            float2 p1 = unpack2(acc[s][r][1]);
            int row = row0 + rg * 4 + r;
            float4 o = make_float4(p0.x + bi.x, p0.y + bi.y, p1.x + bi.z, p1.y + bi.w);
            *(float4*)(C + ((size_t)b * rows + row) * DD + col0 + cg * 4) = o;
        }
    }
}

// ---- mid: uproj (512 blks, 128x64 tiles, 3/SM) + usum (16) + scores (128) + lists (8)
__global__ __launch_bounds__(256, 3) void k_mid(const float* __restrict__ W_h,
                                                const float* __restrict__ W_t,
                                                const int* __restrict__ eid)
{
    __shared__ __align__(16) char buf[25472];
    int blk = blockIdx.x;
    int tid = threadIdx.x;

    if (blk < 512) {
        // ---- uproj: u tile 128 rows x 64 cols, K=32 ----
        int ct = blk & 3;
        int g = blk >> 2;
        int s = g >> 6, b = (g >> 3) & 7, h = g & 7;
        const float* Wo = (s ? W_t : W_h) + 3 * 65536 + h * DKK * DD;
        size_t voff = (size_t)b * MM * DD + h * DKK;
        const float* V  = g_v[s] + voff;
        const float* P0 = g_vp[0][s] + voff;
        const float* P1 = g_vp[1][s] + voff;
        const float* P2 = g_vp[2][s] + voff;
        int col0 = ct * 64;
        float (*a_sh)[132] = (float(*)[132])buf;               // 32x132x4 = 16896 B
        float (*w_sh)[64]  = (float(*)[64])(buf + 16896);      // 32x64x4  =  8192 B

        #pragma unroll
        for (int i = 0; i < 4; i++) {      // V 128x32 transposed, 4-partial sum
            int f = tid + i * 256;
            int r = f >> 3;
            int kq = (f & 7) * 4;
            size_t o = (size_t)r * DD + kq;
            float4 a0 = *(const float4*)(V + o);
            float4 a1 = *(const float4*)(P0 + o);
            float4 a2 = *(const float4*)(P1 + o);
            float4 a3 = *(const float4*)(P2 + o);
            a_sh[kq+0][r] = a0.x + a1.x + a2.x + a3.x;
            a_sh[kq+1][r] = a0.y + a1.y + a2.y + a3.y;
            a_sh[kq+2][r] = a0.z + a1.z + a2.z + a3.z;
            a_sh[kq+3][r] = a0.w + a1.w + a2.w + a3.w;
        }
        #pragma unroll
        for (int i = 0; i < 2; i++) {      // Wo 32x64
            int idx = tid + i * 256;
            int kk = idx >> 4;
            int dq = (idx & 15) * 4;
            *(float4*)&w_sh[kk][dq] = *(const float4*)(Wo + (size_t)kk * DD + col0 + dq);
        }
        __syncthreads();

        // warp-uniform: rows in rg = tid>>4 (A broadcast within warp halves)
        int rg = tid >> 4;    // 16 row groups x 8 rows
        int cg = tid & 15;    // 16 col groups x 4 cols
        ull acc[4][4];        // 8 rows (as 4 f32x2 pairs) x 4 cols
        #pragma unroll
        for (int p = 0; p < 4; p++)
            #pragma unroll
            for (int c = 0; c < 4; c++) acc[p][c] = 0ull;
        #pragma unroll
        for (int kk = 0; kk < 32; kk++) {
            ulonglong2 A0 = *(const ulonglong2*)&a_sh[kk][rg * 8];
            ulonglong2 A1 = *(const ulonglong2*)&a_sh[kk][rg * 8 + 4];
            float4 wv = *(const float4*)&w_sh[kk][cg * 4];
            ull w0 = bcast2(wv.x), w1 = bcast2(wv.y), w2 = bcast2(wv.z), w3 = bcast2(wv.w);
            fma2(acc[0][0], A0.x, w0); fma2(acc[0][1], A0.x, w1);
            fma2(acc[0][2], A0.x, w2); fma2(acc[0][3], A0.x, w3);
            fma2(acc[1][0], A0.y, w0); fma2(acc[1][1], A0.y, w1);
            fma2(acc[1][2], A0.y, w2); fma2(acc[1][3], A0.y, w3);
            fma2(acc[2][0], A1.x, w0); fma2(acc[2][1], A1.x, w1);
            fma2(acc[2][2], A1.x, w2); fma2(acc[2][3], A1.x, w3);
            fma2(acc[3][0], A1.y, w0); fma2(acc[3][1], A1.y, w1);
            fma2(acc[3][2], A1.y, w2); fma2(acc[3][3], A1.y, w3);
        }
        float* U = g_u[s] + ((size_t)(b * HH + h) * MM) * DD;
        #pragma unroll
        for (int p = 0; p < 4; p++) {
            float2 u0 = unpack2(acc[p][0]), u1 = unpack2(acc[p][1]);
            float2 u2 = unpack2(acc[p][2]), u3 = unpack2(acc[p][3]);
            int re = rg * 8 + 2 * p;
            *(float4*)(U + (size_t)re * DD + col0 + cg * 4) =
                make_float4(u0.x, u1.x, u2.x, u3.x);
            *(float4*)(U + (size_t)(re + 1) * DD + col0 + cg * 4) =
                make_float4(u0.y, u1.y, u2.y, u3.y);
        }
    } else if (blk < 528) {
        int id = blk - 512;
        int b = id & 7, s = id >> 3;
        const float* Wo = (s ? W_t : W_h) + 3 * 65536;
        float* vs = (float*)buf;
        int d = tid;
        size_t voff = (size_t)b * MM * DD;
        const float* v  = g_v[s] + voff;
        const float* p0 = g_vp[0][s] + voff;
        const float* p1 = g_vp[1][s] + voff;
        const float* p2 = g_vp[2][s] + voff;
        float sum = 0.f;
        for (int m = 0; m < MM; m++) {
            size_t o = (size_t)m * DD + d;
            sum += v[o] + p0[o] + p1[o] + p2[o];
        }
        vs[d] = sum;
        __syncthreads();
        float o = 0.f;
        for (int k = 0; k < DD; k++) o = fmaf(vs[k], Wo[(size_t)k * DD + d], o);
        g_usum[s][b * DD + d] = o;
    } else if (blk < 656) {
        int t = blk - 528;
        int h = t & 7, b = (t >> 3) & 7, s = t >> 6;
        float (*qs)[DKK + 1] = (float(*)[DKK + 1])buf;
        float (*ks)[DKK + 1] = (float(*)[DKK + 1])(buf + EE * (DKK + 1) * 4);
        size_t qoff = (size_t)b * EE * DD + h * DKK;
        size_t koff = (size_t)b * MM * DD + h * DKK;
        const float* q  = g_q[s] + qoff;
        const float* q0 = g_qp[0][s] + qoff;
        const float* q1 = g_qp[1][s] + qoff;
        const float* q2 = g_qp[2][s] + qoff;
        const float* k  = g_k[s] + koff;
        const float* k0 = g_kp[0][s] + koff;
        const float* k1 = g_kp[1][s] + koff;
        const float* k2 = g_kp[2][s] + koff;
        for (int i = tid; i < EE * DKK; i += 256) {
            int r = i >> 5, c = i & 31;
            size_t o = (size_t)r * DD + c;
            qs[r][c] = q[o] + q0[o] + q1[o] + q2[o];
        }
        for (int i = tid; i < MM * DKK; i += 256) {
            int r = i >> 5, c = i & 31;
            size_t o = (size_t)r * DD + c;
            ks[r][c] = k[o] + k0[o] + k1[o] + k2[o];
        }
        __syncthreads();
        int j = tid & 63;
        int m0 = tid >> 6;
        float* Sbase = g_S[s] + (size_t)(b * HH + h) * MM * EE;
        const float scale = 0.17677669529663687f;
        for (int m = m0; m < MM; m += 4) {
            float acc = 0.f;
            #pragma unroll
            for (int c = 0; c < DKK; c++) acc = fmaf(qs[j][c], ks[m][c], acc);
            Sbase[(size_t)m * EE + j] = acc * scale;
        }
    } else {
        int b = blk - 656;
        if (tid < EE) {
            int e = tid;
            int cnt = 0;
            for (int m = 0; m < MM; m++)
                if (eid[b*MM + m] == e) g_list[(b*EE + e)*MM + cnt++] = m;
            g_cnt[b*EE + e] = cnt;
        }
    }
}

// -------- fused output (j-split): online stats, u staged in smem ---------------
__global__ __launch_bounds__(256, 3) void k_out3(const float* __restrict__ b_h,
                                                 const float* __restrict__ b_t,
                                                 float* __restrict__ out)
{
    int i = blockIdx.x;
    int b = blockIdx.y;
    int z = blockIdx.z;
    int s = z >> 1;
    int j0 = (z & 1) * 32;
    const float* bo = (s ? b_t : b_h) + 3 * 256;
    float* outS = out + (size_t)s * SETHALF + (size_t)b * NPAIR * DD;
    int tid = threadIdx.x;
    int cnt = g_cnt[b * EE + i];

    if (cnt == 0) {
        const float* us = g_usum[s] + b * DD;
        for (int idx = tid; idx < 32 * 64; idx += 256) {
            int j = j0 + (idx >> 6);
            int q = idx & 63;
            float4 bo4 = *(const float4*)(bo + q * 4);
            float4 u4 = *(const float4*)(us + q * 4);
            float4 o = make_float4(bo4.x + u4.x * (1.0f/128.0f),
                                   bo4.y + u4.y * (1.0f/128.0f),
                                   bo4.z + u4.z * (1.0f/128.0f),
                                   bo4.w + u4.w * (1.0f/128.0f));
            int pair = (s == 0) ? (i * EE + j) : (j * EE + i);
            *(float4*)(outS + (size_t)pair * DD + q * 4) = o;
        }
        return;
    }

    __shared__ int lst[MM];
    __shared__ float mx[HH][32];
    __shared__ float rs[HH][32];
    __shared__ float wsh[HH][4][32];
    __shared__ float4 sU[HH][4][64];   // 32 KB

    for (int t = tid; t < cnt; t += 256) lst[t] = g_list[(b * EE + i) * MM + t];
    __syncthreads();

    const float* Sb = g_S[s] + (size_t)(b * HH) * MM * EE;

    {
        int h = tid >> 5;
        int jl = tid & 31;
        const float* Sh = Sb + (size_t)h * MM * EE + j0 + jl;
        float m_ = -1e30f, se = 0.f;
        for (int c = 0; c < cnt; c++) {
            float v = Sh[(size_t)lst[c] * EE];
            float nm = fmaxf(m_, v);
            se = se * __expf(m_ - nm) + __expf(v - nm);
            m_ = nm;
        }
        mx[h][jl] = m_;
        rs[h][jl] = 1.0f / se;
    }
    __syncthreads();

    int dq = tid & 63;
    int jg = tid >> 6;
    ull acc[8][2];
    #pragma unroll
    for (int jj = 0; jj < 8; jj++) { acc[jj][0] = 0ull; acc[jj][1] = 0ull; }

    const float* Ug = g_u[s] + (size_t)(b * HH) * MM * DD;

    for (int base = 0; base < cnt; base += 4) {
        int ce = min(4, cnt - base);
        #pragma unroll
        for (int rr = 0; rr < 8; rr++) {
            int t = tid + rr * 256;
            int h = t >> 8, c = (t >> 6) & 3, q = t & 63;
            if (c < ce)
                sU[h][c][q] = *(const float4*)(Ug + ((size_t)h * MM + lst[base + c]) * DD + q * 4);
        }
        for (int t = tid; t < HH * 4 * 32; t += 256) {
            int h = t >> 7, c = (t >> 5) & 3, jl = t & 31;
            if (c < ce) {
                float sv = Sb[((size_t)h * MM + lst[base + c]) * EE + j0 + jl];
                wsh[h][c][jl] = __expf(sv - mx[h][jl]) * rs[h][jl];
            }
        }
        __syncthreads();
        for (int c = 0; c < ce; c++) {
            #pragma unroll
            for (int h = 0; h < HH; h++) {
                ulonglong2 U = *(const ulonglong2*)&sU[h][c][dq];
                const float* wr = &wsh[h][c][jg * 8];
                float4 wa = *(const float4*)(wr);
                float4 wb = *(const float4*)(wr + 4);
                ull w0 = bcast2(wa.x), w1 = bcast2(wa.y), w2 = bcast2(wa.z), w3 = bcast2(wa.w);
                fma2(acc[0][0], w0, U.x); fma2(acc[0][1], w0, U.y);
                fma2(acc[1][0], w1, U.x); fma2(acc[1][1], w1, U.y);
                fma2(acc[2][0], w2, U.x); fma2(acc[2][1], w2, U.y);
                fma2(acc[3][0], w3, U.x); fma2(acc[3][1], w3, U.y);
                ull w4 = bcast2(wb.x), w5 = bcast2(wb.y), w6 = bcast2(wb.z), w7 = bcast2(wb.w);
                fma2(acc[4][0], w4, U.x); fma2(acc[4][1], w4, U.y);
                fma2(acc[5][0], w5, U.x); fma2(acc[5][1], w5, U.y);
                fma2(acc[6][0], w6, U.x); fma2(acc[6][1], w6, U.y);
                fma2(acc[7][0], w7, U.x); fma2(acc[7][1], w7, U.y);
            }
        }
        __syncthreads();
    }

    float4 bo4 = *(const float4*)(bo + dq * 4);
    #pragma unroll
    for (int jj = 0; jj < 8; jj++) {
        int j = j0 + jg * 8 + jj;
        int pair = (s == 0) ? (i * EE + j) : (j * EE + i);
        float2 p0 = unpack2(acc[jj][0]);
        float2 p1 = unpack2(acc[jj][1]);
        float4 o = make_float4(p0.x + bo4.x, p0.y + bo4.y, p1.x + bo4.z, p1.y + bo4.w);
        *(float4*)(outS + (size_t)pair * DD + dq * 4) = o;
    }
}

// ---------------- launch ----------------
extern "C" void kernel_launch(void* const* d_in, const int* in_sizes, int n_in,
                              void* d_out, int out_size) {
    const float* entities  = (const float*)d_in[0];
    const float* mentions  = (const float*)d_in[1];
    const float* sentences = (const float*)d_in[2];
    const int*   sent_ids  = (const int*)d_in[3];
    const int*   eid       = (const int*)d_in[4];
    const float* W_h       = (const float*)d_in[5];
    const float* b_h       = (const float*)d_in[6];
    const float* W_t       = (const float*)d_in[7];
    const float* b_t       = (const float*)d_in[8];
    float* out = (float*)d_out;

    k_gemm_all<<<dim3(16, 5, BB), 256>>>(entities, mentions, sentences, sent_ids,
                                         W_h, b_h, W_t, b_t);
    k_mid<<<664, 256>>>(W_h, W_t, eid);
    k_out3<<<dim3(EE, BB, 4), 256>>>(b_h, b_t, out);
}

// round 17
// speedup vs baseline: 1.0552x; 1.0078x over previous
#include <cuda_runtime.h>

#define BB 8
#define EE 64
#define MM 128
#define DD 256
#define HH 8
#define DKK 32
#define NPAIR (EE*EE)
#define SETHALF (BB*NPAIR*DD)

typedef unsigned long long ull;

// ---- packed fp32x2 helpers ----
__device__ __forceinline__ void fma2(ull &d, ull a, ull b) {
    asm("fma.rn.f32x2 %0, %1, %2, %0;" : "+l"(d) : "l"(a), "l"(b));
}
__device__ __forceinline__ ull bcast2(float x) {
    ull d;
    asm("mov.b64 %0, {%1, %1};" : "=l"(d) : "r"(__float_as_uint(x)));
    return d;
}
__device__ __forceinline__ float2 unpack2(ull v) {
    float2 r;
    asm("mov.b64 {%0, %1}, %2;" : "=f"(r.x), "=f"(r.y) : "l"(v));
    return r;
}
// ---- cp.async ----
__device__ __forceinline__ void cp_async16(unsigned dst, const void* src) {
    asm volatile("cp.async.cg.shared.global [%0], [%1], 16;" :: "r"(dst), "l"(src));
}
__device__ __forceinline__ void cp_commit() { asm volatile("cp.async.commit_group;"); }
__device__ __forceinline__ void cp_wait0()  { asm volatile("cp.async.wait_group 0;" ::: "memory"); }
// ---- PDL ----
__device__ __forceinline__ void pdl_trigger() {
    asm volatile("griddepcontrol.launch_dependents;");
}
__device__ __forceinline__ void pdl_wait() {
    asm volatile("griddepcontrol.wait;" ::: "memory");
}

// ---------------- scratch ----------------
__device__ float g_q[2][BB*EE*DD];
__device__ float g_k[2][BB*MM*DD];
__device__ float g_v[2][BB*MM*DD];
__device__ float g_qp[3][2][BB*EE*DD];   // K-split partials kh=1..3
__device__ float g_kp[3][2][BB*MM*DD];
__device__ float g_vp[3][2][BB*MM*DD];
__device__ float g_u[2][BB*HH*MM*DD];
__device__ float g_S[2][BB*HH*MM*EE];    // [s][b][h][m][j], j innermost
__device__ float g_usum[2][BB*DD];
__device__ int   g_cnt[BB*EE];
__device__ int   g_list[BB*EE*MM];

// ---- merged projections; 4-way K-split + list building; PDL primary ----
// grid (16, 6, 8): y 0..4 = job/rowTile (x = colTile + kh*4); y==5 & x==0 = lists.
__global__ __launch_bounds__(256, 3) void k_gemm_all(
    const float* __restrict__ entities, const float* __restrict__ mentions,
    const float* __restrict__ sentences, const int* __restrict__ sent_ids,
    const int* __restrict__ eid,
    const float* __restrict__ W_h, const float* __restrict__ b_h,
    const float* __restrict__ W_t, const float* __restrict__ b_t)
{
    pdl_trigger();   // let k_mid launch onto freed SMs; its gemm-reads sit behind a wait
    __shared__ float a_sh[2][32][68];
    __shared__ float w_sh[2][2][32][64];
    int b = blockIdx.z;
    int y = blockIdx.y;
    int x = blockIdx.x;
    int colTile = x & 3;
    int kh = x >> 2;
    int tid = threadIdx.x;

    if (y == 5) {
        if (x == 0 && tid < EE) {
            int e = tid;
            int cnt = 0;
            for (int m = 0; m < MM; m++)
                if (eid[b*MM + m] == e) g_list[(b*EE + e)*MM + cnt++] = m;
            g_cnt[b*EE + e] = cnt;
        }
        return;
    }

    int job, rowTile;
    if (y == 0) { job = 0; rowTile = 0; }
    else if (y <= 2) { job = 1; rowTile = y - 1; }
    else { job = 2; rowTile = y - 3; }
    const float* A; int rows, woff, boff;
    float *C0, *C1;
    bool indirect = false;
    switch (job) {
      case 0:
        A = entities; rows = EE;  woff = 0;      boff = 0;
        C0 = kh ? g_qp[kh-1][0] : g_q[0]; C1 = kh ? g_qp[kh-1][1] : g_q[1]; break;
      case 1:
        A = nullptr;  rows = MM;  woff = 65536;  boff = 256; indirect = true;
        C0 = kh ? g_kp[kh-1][0] : g_k[0]; C1 = kh ? g_kp[kh-1][1] : g_k[1]; break;
      default:
        A = mentions; rows = MM;  woff = 131072; boff = 512;
        C0 = kh ? g_vp[kh-1][0] : g_v[0]; C1 = kh ? g_vp[kh-1][1] : g_v[1]; break;
    }
    int row0 = rowTile * 64;
    int col0 = colTile * 64;
    int kbase = kh * 64;

    int kqI[2], cI[2];
    const float* rp[2];
    #pragma unroll
    for (int i = 0; i < 2; i++) {
        int f = tid * 2 + i;
        int r = f >> 3;
        kqI[i] = (f & 7) * 4;
        cI[i]  = r ^ (((kqI[i] >> 3) & 3) << 3);
        if (indirect) {
            int sid = sent_ids[b * MM + row0 + r];
            rp[i] = sentences + ((size_t)(b * 32 + sid)) * DD + kbase + kqI[i];
        } else {
            rp[i] = A + ((size_t)b * rows + row0 + r) * DD + kbase + kqI[i];
        }
    }
    unsigned wbase = (unsigned)__cvta_generic_to_shared(&w_sh[0][0][0][0]);
    const unsigned WBUF = 2u * 32u * 64u * 4u;
    unsigned wdst[4];
    const float* wp[4];
    #pragma unroll
    for (int j = 0; j < 4; j++) {
        int idx = tid + j * 256;
        int ws = idx >> 9;
        int rem = idx & 511;
        int wk = rem >> 4;
        int wd = (rem & 15) * 4;
        wdst[j] = wbase + (unsigned)(((ws * 32 + wk) * 64 + wd) * 4);
        const float* Wsel = (ws ? W_t : W_h) + woff;
        wp[j] = Wsel + (size_t)(kbase + wk) * DD + col0 + wd;
    }

    int rg = tid >> 4;
    int cg = tid & 15;
    int rb = rg * 4;
    ull acc[2][4][2];
    #pragma unroll
    for (int s = 0; s < 2; s++)
        #pragma unroll
        for (int r = 0; r < 4; r++)
            { acc[s][r][0] = 0ull; acc[s][r][1] = 0ull; }

    #pragma unroll
    for (int j = 0; j < 4; j++) cp_async16(wdst[j], wp[j]);
    cp_commit();
    {
        float4 pa0 = *(const float4*)(rp[0]);
        float4 pa1 = *(const float4*)(rp[1]);
        a_sh[0][kqI[0]+0][cI[0]] = pa0.x; a_sh[0][kqI[0]+1][cI[0]] = pa0.y;
        a_sh[0][kqI[0]+2][cI[0]] = pa0.z; a_sh[0][kqI[0]+3][cI[0]] = pa0.w;
        a_sh[0][kqI[1]+0][cI[1]] = pa1.x; a_sh[0][kqI[1]+1][cI[1]] = pa1.y;
        a_sh[0][kqI[1]+2][cI[1]] = pa1.z; a_sh[0][kqI[1]+3][cI[1]] = pa1.w;
    }
    cp_wait0();
    __syncthreads();

    float4 pa[2];
    #pragma unroll
    for (int kc = 0; kc < 2; kc++) {
        int buf = kc & 1;
        int nb = buf ^ 1;
        if (kc < 1) {
            int k0n = 32;
            #pragma unroll
            for (int j = 0; j < 4; j++)
                cp_async16(wdst[j] + (unsigned)nb * WBUF, wp[j] + (size_t)k0n * DD);
            cp_commit();
            #pragma unroll
            for (int i = 0; i < 2; i++) pa[i] = *(const float4*)(rp[i] + k0n);
        }
        #pragma unroll
        for (int kk = 0; kk < 24; kk++) {
            int cs = rb ^ (((kk >> 3) & 3) << 3);
            float4 Af = *(const float4*)&a_sh[buf][kk][cs];
            ulonglong2 W0 = *(const ulonglong2*)&w_sh[buf][0][kk][cg * 4];
            ulonglong2 W1 = *(const ulonglong2*)&w_sh[buf][1][kk][cg * 4];
            ull a0 = bcast2(Af.x), a1 = bcast2(Af.y), a2 = bcast2(Af.z), a3 = bcast2(Af.w);
            fma2(acc[0][0][0], a0, W0.x); fma2(acc[0][0][1], a0, W0.y);
            fma2(acc[0][1][0], a1, W0.x); fma2(acc[0][1][1], a1, W0.y);
            fma2(acc[0][2][0], a2, W0.x); fma2(acc[0][2][1], a2, W0.y);
            fma2(acc[0][3][0], a3, W0.x); fma2(acc[0][3][1], a3, W0.y);
            fma2(acc[1][0][0], a0, W1.x); fma2(acc[1][0][1], a0, W1.y);
            fma2(acc[1][1][0], a1, W1.x); fma2(acc[1][1][1], a1, W1.y);
            fma2(acc[1][2][0], a2, W1.x); fma2(acc[1][2][1], a2, W1.y);
            fma2(acc[1][3][0], a3, W1.x); fma2(acc[1][3][1], a3, W1.y);
        }
        if (kc < 1) {
            #pragma unroll
            for (int i = 0; i < 2; i++) {
                a_sh[nb][kqI[i]+0][cI[i]] = pa[i].x; a_sh[nb][kqI[i]+1][cI[i]] = pa[i].y;
                a_sh[nb][kqI[i]+2][cI[i]] = pa[i].z; a_sh[nb][kqI[i]+3][cI[i]] = pa[i].w;
            }
        }
        #pragma unroll
        for (int kk = 24; kk < 32; kk++) {
            int cs = rb ^ (((kk >> 3) & 3) << 3);
            float4 Af = *(const float4*)&a_sh[buf][kk][cs];
            ulonglong2 W0 = *(const ulonglong2*)&w_sh[buf][0][kk][cg * 4];
            ulonglong2 W1 = *(const ulonglong2*)&w_sh[buf][1][kk][cg * 4];
            ull a0 = bcast2(Af.x), a1 = bcast2(Af.y), a2 = bcast2(Af.z), a3 = bcast2(Af.w);
            fma2(acc[0][0][0], a0, W0.x); fma2(acc[0][0][1], a0, W0.y);
            fma2(acc[0][1][0], a1, W0.x); fma2(acc[0][1][1], a1, W0.y);
            fma2(acc[0][2][0], a2, W0.x); fma2(acc[0][2][1], a2, W0.y);
            fma2(acc[0][3][0], a3, W0.x); fma2(acc[0][3][1], a3, W0.y);
            fma2(acc[1][0][0], a0, W1.x); fma2(acc[1][0][1], a0, W1.y);
            fma2(acc[1][1][0], a1, W1.x); fma2(acc[1][1][1], a1, W1.y);
            fma2(acc[1][2][0], a2, W1.x); fma2(acc[1][2][1], a2, W1.y);
            fma2(acc[1][3][0], a3, W1.x); fma2(acc[1][3][1], a3, W1.y);
        }
        if (kc < 1) cp_wait0();
        __syncthreads();
    }

    #pragma unroll
    for (int s = 0; s < 2; s++) {
        float* C = s ? C1 : C0;
        float4 bi = make_float4(0.f, 0.f, 0.f, 0.f);
        if (kh == 0) {
            const float* bias = (s ? b_t : b_h) + boff;
            bi = *(const float4*)(bias + col0 + cg * 4);
        }
        #pragma unroll
        for (int r = 0; r < 4; r++) {
            float2 p0 = unpack2(acc[s][r][0]);
            float2 p1 = unpack2(acc[s][r][1]);
            int row = row0 + rg * 4 + r;
            float4 o = make_float4(p0.x + bi.x, p0.y + bi.y, p1.x + bi.z, p1.y + bi.w);
            *(float4*)(C + ((size_t)b * rows + row) * DD + col0 + cg * 4) = o;
        }
    }
}

// ---- mid: uproj (512) + usum (16) + scores (128); PDL: W staged pre-wait ----
__global__ __launch_bounds__(256, 3) void k_mid(const float* __restrict__ W_h,
                                                const float* __restrict__ W_t)
{
    __shared__ __align__(16) char buf[25472];
    int blk = blockIdx.x;
    int tid = threadIdx.x;

    if (blk < 512) {
        int ct = blk & 3;
        int g = blk >> 2;
        int s = g >> 6, b = (g >> 3) & 7, h = g & 7;
        const float* Wo = (s ? W_t : W_h) + 3 * 65536 + h * DKK * DD;
        size_t voff = (size_t)b * MM * DD + h * DKK;
        int col0 = ct * 64;
        float (*a_sh)[132] = (float(*)[132])buf;
        float (*w_sh)[64]  = (float(*)[64])(buf + 16896);

        // W staging first: weights are kernel inputs, legal BEFORE the PDL wait
        #pragma unroll
        for (int i = 0; i < 2; i++) {
            int idx = tid + i * 256;
            int kk = idx >> 4;
            int dq = (idx & 15) * 4;
            *(float4*)&w_sh[kk][dq] = *(const float4*)(Wo + (size_t)kk * DD + col0 + dq);
        }
        pdl_wait();       // gemm outputs now visible
        pdl_trigger();    // release k_out3 (gemm guaranteed complete past this point)

        const float* V  = g_v[s] + voff;
        const float* P0 = g_vp[0][s] + voff;
        const float* P1 = g_vp[1][s] + voff;
        const float* P2 = g_vp[2][s] + voff;
        #pragma unroll
        for (int i = 0; i < 4; i++) {
            int f = tid + i * 256;
            int r = f >> 3;
            int kq = (f & 7) * 4;
            size_t o = (size_t)r * DD + kq;
            float4 a0 = *(const float4*)(V + o);
            float4 a1 = *(const float4*)(P0 + o);
            float4 a2 = *(const float4*)(P1 + o);
            float4 a3 = *(const float4*)(P2 + o);
            a_sh[kq+0][r] = a0.x + a1.x + a2.x + a3.x;
            a_sh[kq+1][r] = a0.y + a1.y + a2.y + a3.y;
            a_sh[kq+2][r] = a0.z + a1.z + a2.z + a3.z;
            a_sh[kq+3][r] = a0.w + a1.w + a2.w + a3.w;
        }
        __syncthreads();

        int rg = tid >> 4;
        int cg = tid & 15;
        ull acc[4][4];
        #pragma unroll
        for (int p = 0; p < 4; p++)
            #pragma unroll
            for (int c = 0; c < 4; c++) acc[p][c] = 0ull;
        #pragma unroll
        for (int kk = 0; kk < 32; kk++) {
            ulonglong2 A0 = *(const ulonglong2*)&a_sh[kk][rg * 8];
            ulonglong2 A1 = *(const ulonglong2*)&a_sh[kk][rg * 8 + 4];
            float4 wv = *(const float4*)&w_sh[kk][cg * 4];
            ull w0 = bcast2(wv.x), w1 = bcast2(wv.y), w2 = bcast2(wv.z), w3 = bcast2(wv.w);
            fma2(acc[0][0], A0.x, w0); fma2(acc[0][1], A0.x, w1);
            fma2(acc[0][2], A0.x, w2); fma2(acc[0][3], A0.x, w3);
            fma2(acc[1][0], A0.y, w0); fma2(acc[1][1], A0.y, w1);
            fma2(acc[1][2], A0.y, w2); fma2(acc[1][3], A0.y, w3);
            fma2(acc[2][0], A1.x, w0); fma2(acc[2][1], A1.x, w1);
            fma2(acc[2][2], A1.x, w2); fma2(acc[2][3], A1.x, w3);
            fma2(acc[3][0], A1.y, w0); fma2(acc[3][1], A1.y, w1);
            fma2(acc[3][2], A1.y, w2); fma2(acc[3][3], A1.y, w3);
        }
        float* U = g_u[s] + ((size_t)(b * HH + h) * MM) * DD;
        #pragma unroll
        for (int p = 0; p < 4; p++) {
            float2 u0 = unpack2(acc[p][0]), u1 = unpack2(acc[p][1]);
            float2 u2 = unpack2(acc[p][2]), u3 = unpack2(acc[p][3]);
            int re = rg * 8 + 2 * p;
            *(float4*)(U + (size_t)re * DD + col0 + cg * 4) =
                make_float4(u0.x, u1.x, u2.x, u3.x);
            *(float4*)(U + (size_t)(re + 1) * DD + col0 + cg * 4) =
                make_float4(u0.y, u1.y, u2.y, u3.y);
        }
    } else if (blk < 528) {
        pdl_wait();
        pdl_trigger();
        int id = blk - 512;
        int b = id & 7, s = id >> 3;
        const float* Wo = (s ? W_t : W_h) + 3 * 65536;
        float* vs = (float*)buf;
        int d = tid;
        size_t voff = (size_t)b * MM * DD;
        const float* v  = g_v[s] + voff;
        const float* p0 = g_vp[0][s] + voff;
        const float* p1 = g_vp[1][s] + voff;
        const float* p2 = g_vp[2][s] + voff;
        float sum = 0.f;
        for (int m = 0; m < MM; m++) {
            size_t o = (size_t)m * DD + d;
            sum += v[o] + p0[o] + p1[o] + p2[o];
        }
        vs[d] = sum;
        __syncthreads();
        float o = 0.f;
        for (int k = 0; k < DD; k++) o = fmaf(vs[k], Wo[(size_t)k * DD + d], o);
        g_usum[s][b * DD + d] = o;
    } else {
        pdl_wait();
        pdl_trigger();
        int t = blk - 528;
        int h = t & 7, b = (t >> 3) & 7, s = t >> 6;
        float (*qs)[DKK + 1] = (float(*)[DKK + 1])buf;
        float (*ks)[DKK + 1] = (float(*)[DKK + 1])(buf + EE * (DKK + 1) * 4);
        size_t qoff = (size_t)b * EE * DD + h * DKK;
        size_t koff = (size_t)b * MM * DD + h * DKK;
        const float* q  = g_q[s] + qoff;
        const float* q0 = g_qp[0][s] + qoff;
        const float* q1 = g_qp[1][s] + qoff;
        const float* q2 = g_qp[2][s] + qoff;
        const float* k  = g_k[s] + koff;
        const float* k0 = g_kp[0][s] + koff;
        const float* k1 = g_kp[1][s] + koff;
        const float* k2 = g_kp[2][s] + koff;
        for (int i = tid; i < EE * DKK; i += 256) {
            int r = i >> 5, c = i & 31;
            size_t o = (size_t)r * DD + c;
            qs[r][c] = q[o] + q0[o] + q1[o] + q2[o];
        }
        for (int i = tid; i < MM * DKK; i += 256) {
            int r = i >> 5, c = i & 31;
            size_t o = (size_t)r * DD + c;
            ks[r][c] = k[o] + k0[o] + k1[o] + k2[o];
        }
        __syncthreads();
        int j = tid & 63;
        int m0 = tid >> 6;
        float* Sbase = g_S[s] + (size_t)(b * HH + h) * MM * EE;
        const float scale = 0.17677669529663687f;
        for (int m = m0; m < MM; m += 4) {
            float acc = 0.f;
            #pragma unroll
            for (int c = 0; c < DKK; c++) acc = fmaf(qs[j][c], ks[m][c], acc);
            Sbase[(size_t)m * EE + j] = acc * scale;
        }
    }
}

// -------- fused output (j-split): lst/cnt pre-wait (gemm outputs), then PDL wait ----
__global__ __launch_bounds__(256, 3) void k_out3(const float* __restrict__ b_h,
                                                 const float* __restrict__ b_t,
                                                 float* __restrict__ out)
{
    int i = blockIdx.x;
    int b = blockIdx.y;
    int z = blockIdx.z;
    int s = z >> 1;
    int j0 = (z & 1) * 32;
    const float* bo = (s ? b_t : b_h) + 3 * 256;
    float* outS = out + (size_t)s * SETHALF + (size_t)b * NPAIR * DD;
    int tid = threadIdx.x;

    __shared__ int lst[MM];
    __shared__ float mx[HH][32];
    __shared__ float rs[HH][32];
    __shared__ float wsh[HH][4][32];
    __shared__ float4 sU[HH][4][64];   // 32 KB

    // gemm outputs (mid's trigger fires only after gemm completion) — safe pre-wait
    int cnt = g_cnt[b * EE + i];
    for (int t = tid; t < cnt; t += 256) lst[t] = g_list[(b * EE + i) * MM + t];
    __syncthreads();

    pdl_wait();   // mid outputs (S, u, usum) now visible

    if (cnt == 0) {
        const float* us = g_usum[s] + b * DD;
        for (int idx = tid; idx < 32 * 64; idx += 256) {
            int j = j0 + (idx >> 6);
            int q = idx & 63;
            float4 bo4 = *(const float4*)(bo + q * 4);
            float4 u4 = *(const float4*)(us + q * 4);
            float4 o = make_float4(bo4.x + u4.x * (1.0f/128.0f),
                                   bo4.y + u4.y * (1.0f/128.0f),
                                   bo4.z + u4.z * (1.0f/128.0f),
                                   bo4.w + u4.w * (1.0f/128.0f));
            int pair = (s == 0) ? (i * EE + j) : (j * EE + i);
            *(float4*)(outS + (size_t)pair * DD + q * 4) = o;
        }
        return;
    }

    const float* Sb = g_S[s] + (size_t)(b * HH) * MM * EE;

    {
        int h = tid >> 5;
        int jl = tid & 31;
        const float* Sh = Sb + (size_t)h * MM * EE + j0 + jl;
        float m_ = -1e30f, se = 0.f;
        for (int c = 0; c < cnt; c++) {
            float v = Sh[(size_t)lst[c] * EE];
            float nm = fmaxf(m_, v);
            se = se * __expf(m_ - nm) + __expf(v - nm);
            m_ = nm;
        }
        mx[h][jl] = m_;
        rs[h][jl] = 1.0f / se;
    }
    __syncthreads();

    int dq = tid & 63;
    int jg = tid >> 6;
    ull acc[8][2];
    #pragma unroll
    for (int jj = 0; jj < 8; jj++) { acc[jj][0] = 0ull; acc[jj][1] = 0ull; }

    const float* Ug = g_u[s] + (size_t)(b * HH) * MM * DD;

    for (int base = 0; base < cnt; base += 4) {
        int ce = min(4, cnt - base);
        #pragma unroll
        for (int rr = 0; rr < 8; rr++) {
            int t = tid + rr * 256;
            int h = t >> 8, c = (t >> 6) & 3, q = t & 63;
            if (c < ce)
                sU[h][c][q] = *(const float4*)(Ug + ((size_t)h * MM + lst[base + c]) * DD + q * 4);
        }
        for (int t = tid; t < HH * 4 * 32; t += 256) {
            int h = t >> 7, c = (t >> 5) & 3, jl = t & 31;
            if (c < ce) {
                float sv = Sb[((size_t)h * MM + lst[base + c]) * EE + j0 + jl];
                wsh[h][c][jl] = __expf(sv - mx[h][jl]) * rs[h][jl];
            }
        }
        __syncthreads();
        for (int c = 0; c < ce; c++) {
            #pragma unroll
            for (int h = 0; h < HH; h++) {
                ulonglong2 U = *(const ulonglong2*)&sU[h][c][dq];
                const float* wr = &wsh[h][c][jg * 8];
                float4 wa = *(const float4*)(wr);
                float4 wb = *(const float4*)(wr + 4);
                ull w0 = bcast2(wa.x), w1 = bcast2(wa.y), w2 = bcast2(wa.z), w3 = bcast2(wa.w);
                fma2(acc[0][0], w0, U.x); fma2(acc[0][1], w0, U.y);
                fma2(acc[1][0], w1, U.x); fma2(acc[1][1], w1, U.y);
                fma2(acc[2][0], w2, U.x); fma2(acc[2][1], w2, U.y);
                fma2(acc[3][0], w3, U.x); fma2(acc[3][1], w3, U.y);
                ull w4 = bcast2(wb.x), w5 = bcast2(wb.y), w6 = bcast2(wb.z), w7 = bcast2(wb.w);
                fma2(acc[4][0], w4, U.x); fma2(acc[4][1], w4, U.y);
                fma2(acc[5][0], w5, U.x); fma2(acc[5][1], w5, U.y);
                fma2(acc[6][0], w6, U.x); fma2(acc[6][1], w6, U.y);
                fma2(acc[7][0], w7, U.x); fma2(acc[7][1], w7, U.y);
            }
        }
        __syncthreads();
    }

    float4 bo4 = *(const float4*)(bo + dq * 4);
    #pragma unroll
    for (int jj = 0; jj < 8; jj++) {
        int j = j0 + jg * 8 + jj;
        int pair = (s == 0) ? (i * EE + j) : (j * EE + i);
        float2 p0 = unpack2(acc[jj][0]);
        float2 p1 = unpack2(acc[jj][1]);
        float4 o = make_float4(p0.x + bo4.x, p0.y + bo4.y, p1.x + bo4.z, p1.y + bo4.w);
        *(float4*)(outS + (size_t)pair * DD + dq * 4) = o;
    }
}

// ---------------- launch (PDL chain) ----------------
extern "C" void kernel_launch(void* const* d_in, const int* in_sizes, int n_in,
                              void* d_out, int out_size) {
    const float* entities  = (const float*)d_in[0];
    const float* mentions  = (const float*)d_in[1];
    const float* sentences = (const float*)d_in[2];
    const int*   sent_ids  = (const int*)d_in[3];
    const int*   eid       = (const int*)d_in[4];
    const float* W_h       = (const float*)d_in[5];
    const float* b_h       = (const float*)d_in[6];
    const float* W_t       = (const float*)d_in[7];
    const float* b_t       = (const float*)d_in[8];
    float* out = (float*)d_out;

    cudaLaunchAttribute pdl[1];
    pdl[0].id = cudaLaunchAttributeProgrammaticStreamSerialization;
    pdl[0].val.programmaticStreamSerializationAllowed = 1;

    cudaLaunchConfig_t c1 = {};
    c1.gridDim = dim3(16, 6, BB); c1.blockDim = dim3(256, 1, 1);
    cudaLaunchKernelEx(&c1, k_gemm_all, entities, mentions, sentences, sent_ids, eid,
                       W_h, b_h, W_t, b_t);

    cudaLaunchConfig_t c2 = {};
    c2.gridDim = dim3(656, 1, 1); c2.blockDim = dim3(256, 1, 1);
    c2.attrs = pdl; c2.numAttrs = 1;
    cudaLaunchKernelEx(&c2, k_mid, W_h, W_t);

    cudaLaunchConfig_t c3 = {};
    c3.gridDim = dim3(EE, BB, 4); c3.blockDim = dim3(256, 1, 1);
    c3.attrs = pdl; c3.numAttrs = 1;
    cudaLaunchKernelEx(&c3, k_out3, b_h, b_t, out);
}